// round 2
// baseline (speedup 1.0000x reference)
#include <cuda_runtime.h>
#include <cuda_bf16.h>
#include <cstdint>
#include <cstdio>

// Problem constants
#define BATCH 32
#define SEQ   512
#define DIM   512
#define HEADS 8
#define DK    64
#define FF    200
#define MTOT  (BATCH*SEQ)        // 16384
#define SD    (SEQ*DIM)          // 262144
#define LN_EPS 1e-5f

// ---------------- scratch (device globals; no allocation allowed) -------------
__device__ float g_q [MTOT*DIM];
__device__ float g_k [MTOT*DIM];
__device__ float g_v [MTOT*DIM];
__device__ float g_cc[MTOT*DIM];
__device__ float g_y0[MTOT*DIM];
__device__ float g_y1[MTOT*DIM];
__device__ float g_z [MTOT*DIM];
__device__ float g_y2[MTOT*DIM];
__device__ float g_f1[MTOT*FF];
__device__ float g_f2[MTOT*FF];
__device__ float g_psum[BATCH*64];
__device__ float g_psq [BATCH*64];
__device__ float g_mean[BATCH];
__device__ float g_rstd[BATCH];

// ---------------- generic tiled GEMM: C[M,N] = A[M,K] * B[N,K]^T + bias (+res) (relu) ----
// BM=BN=128, BK=16, 256 threads, 8x8 per thread (interleaved 16-stride mapping)
__global__ void gemm_kernel(const float* __restrict__ A, const float* __restrict__ B,
                            const float* __restrict__ bias, const float* __restrict__ res,
                            float* __restrict__ C, int M, int N, int K, int relu)
{
    __shared__ float As[16][132];
    __shared__ float Bs[16][132];
    const int tid = threadIdx.x;
    const int tx = tid & 15, ty = tid >> 4;
    const int m0 = blockIdx.y * 128, n0 = blockIdx.x * 128;
    const int lr  = tid >> 2;        // 0..63
    const int lc4 = (tid & 3) * 4;   // 0,4,8,12

    float acc[8][8];
    #pragma unroll
    for (int i = 0; i < 8; i++)
        #pragma unroll
        for (int j = 0; j < 8; j++) acc[i][j] = 0.f;

    const int KT = (K + 15) >> 4;
    for (int kt = 0; kt < KT; kt++) {
        const int k0 = kt << 4;
        const int kc = k0 + lc4;
        #pragma unroll
        for (int half = 0; half < 2; half++) {
            const int r = lr + half * 64;
            float4 av = make_float4(0.f,0.f,0.f,0.f);
            if (kc < K) av = *(const float4*)(A + (size_t)(m0 + r) * K + kc);
            As[lc4+0][r] = av.x; As[lc4+1][r] = av.y;
            As[lc4+2][r] = av.z; As[lc4+3][r] = av.w;
            const int n = n0 + r;
            float4 bv = make_float4(0.f,0.f,0.f,0.f);
            if (n < N && kc < K) bv = *(const float4*)(B + (size_t)n * K + kc);
            Bs[lc4+0][r] = bv.x; Bs[lc4+1][r] = bv.y;
            Bs[lc4+2][r] = bv.z; Bs[lc4+3][r] = bv.w;
        }
        __syncthreads();
        #pragma unroll
        for (int kk = 0; kk < 16; kk++) {
            float a[8], b[8];
            #pragma unroll
            for (int i = 0; i < 8; i++) a[i] = As[kk][ty + 16*i];
            #pragma unroll
            for (int j = 0; j < 8; j++) b[j] = Bs[kk][tx + 16*j];
            #pragma unroll
            for (int i = 0; i < 8; i++)
                #pragma unroll
                for (int j = 0; j < 8; j++)
                    acc[i][j] = fmaf(a[i], b[j], acc[i][j]);
        }
        __syncthreads();
    }

    #pragma unroll
    for (int i = 0; i < 8; i++) {
        const int m = m0 + ty + 16*i;
        #pragma unroll
        for (int j = 0; j < 8; j++) {
            const int n = n0 + tx + 16*j;
            if (n < N) {
                float v = acc[i][j] + bias[n];
                if (res)  v += res[(size_t)m * N + n];
                if (relu) v = fmaxf(v, 0.f);
                C[(size_t)m * N + n] = v;
            }
        }
    }
}

// ---------------- fused attention: per (b,h) x 64-query tile, online softmax ---
// grid (S/64, B*H), 256 threads. smem: Qs,KsT,Vs,Ps [64][68] + red[64][16] + stats.
__global__ void attn_kernel(const float* __restrict__ Q, const float* __restrict__ Kp,
                            const float* __restrict__ Vp, float* __restrict__ O)
{
    extern __shared__ float sm[];
    float* Qs   = sm;                // [64][68] row=q, col=dk
    float* KsT  = sm + 64*68;        // [64][68] row=dk, col=t
    float* Vs   = sm + 2*64*68;      // [64][68] row=t, col=dk
    float* Ps   = sm + 3*64*68;      // [64][68] row=q, col=t
    float* red  = sm + 4*64*68;      // [64][16]
    float* rowm = red + 64*16;
    float* rowl = rowm + 64;
    float* rowsc= rowl + 64;

    const int tid = threadIdx.x;
    const int tx = tid & 15, ty = tid >> 4;
    const int bh = blockIdx.y;
    const int b  = bh >> 3, h = bh & 7;
    const int q0 = blockIdx.x * 64;
    const size_t baseQ = ((size_t)b * SEQ + q0) * DIM + h * DK;
    const size_t baseK = ((size_t)b * SEQ) * DIM + h * DK;
    const int lr = tid >> 2;         // 0..63 (row)
    const int lc = (tid & 3) * 4;    // 0,4,8,12 (col chunk base)

    // load Q tile once: each thread covers columns lc + 16*i, i=0..3 (16 floats)
    #pragma unroll
    for (int i = 0; i < 4; i++) {
        const int c = lc + 16 * i;
        float4 qv = *(const float4*)(Q + baseQ + (size_t)lr * DIM + c);
        Qs[lr*68 + c + 0] = qv.x; Qs[lr*68 + c + 1] = qv.y;
        Qs[lr*68 + c + 2] = qv.z; Qs[lr*68 + c + 3] = qv.w;
    }
    if (tid < 64) { rowm[tid] = -1e30f; rowl[tid] = 0.f; }

    float o[4][4];
    #pragma unroll
    for (int i = 0; i < 4; i++)
        #pragma unroll
        for (int j = 0; j < 4; j++) o[i][j] = 0.f;

    __syncthreads();

    for (int kt = 0; kt < SEQ/64; kt++) {
        const int t0 = kt * 64;
        // load K (transposed store) and V; full 64x64 coverage per tile
        #pragma unroll
        for (int i = 0; i < 4; i++) {
            const int c = lc + 16 * i;
            float4 kv = *(const float4*)(Kp + baseK + (size_t)(t0 + lr) * DIM + c);
            KsT[(c+0)*68 + lr] = kv.x; KsT[(c+1)*68 + lr] = kv.y;
            KsT[(c+2)*68 + lr] = kv.z; KsT[(c+3)*68 + lr] = kv.w;
            float4 vv = *(const float4*)(Vp + baseK + (size_t)(t0 + lr) * DIM + c);
            Vs[lr*68 + c + 0] = vv.x; Vs[lr*68 + c + 1] = vv.y;
            Vs[lr*68 + c + 2] = vv.z; Vs[lr*68 + c + 3] = vv.w;
        }
        __syncthreads();

        // S = Q * K^T * scale
        float s[4][4];
        #pragma unroll
        for (int i = 0; i < 4; i++)
            #pragma unroll
            for (int j = 0; j < 4; j++) s[i][j] = 0.f;
        #pragma unroll 8
        for (int kk = 0; kk < 64; kk++) {
            float a[4], bb[4];
            #pragma unroll
            for (int i = 0; i < 4; i++) a[i]  = Qs[(ty + 16*i)*68 + kk];
            #pragma unroll
            for (int j = 0; j < 4; j++) bb[j] = KsT[kk*68 + tx + 16*j];
            #pragma unroll
            for (int i = 0; i < 4; i++)
                #pragma unroll
                for (int j = 0; j < 4; j++)
                    s[i][j] = fmaf(a[i], bb[j], s[i][j]);
        }
        #pragma unroll
        for (int i = 0; i < 4; i++)
            #pragma unroll
            for (int j = 0; j < 4; j++) s[i][j] *= 0.125f;

        // tile row max -> red
        #pragma unroll
        for (int i = 0; i < 4; i++) {
            float m01 = fmaxf(s[i][0], s[i][1]);
            float m23 = fmaxf(s[i][2], s[i][3]);
            red[(ty + 16*i)*16 + tx] = fmaxf(m01, m23);
        }
        __syncthreads();
        if (tid < 64) {
            float mo = rowm[tid], mn = mo;
            #pragma unroll
            for (int t = 0; t < 16; t++) mn = fmaxf(mn, red[tid*16 + t]);
            rowsc[tid] = __expf(mo - mn);
            rowm[tid]  = mn;
        }
        __syncthreads();

        // P = exp(S - m), partial row sums
        #pragma unroll
        for (int i = 0; i < 4; i++) {
            const int r = ty + 16*i;
            const float mn = rowm[r];
            float rs = 0.f;
            #pragma unroll
            for (int j = 0; j < 4; j++) {
                float p = __expf(s[i][j] - mn);
                Ps[r*68 + tx + 16*j] = p;
                rs += p;
            }
            red[r*16 + tx] = rs;
        }
        __syncthreads();
        if (tid < 64) {
            float ssum = 0.f;
            #pragma unroll
            for (int t = 0; t < 16; t++) ssum += red[tid*16 + t];
            rowl[tid] = rowl[tid] * rowsc[tid] + ssum;
        }

        // O = O*scale + P*V
        #pragma unroll
        for (int i = 0; i < 4; i++) {
            const float sc = rowsc[ty + 16*i];
            #pragma unroll
            for (int j = 0; j < 4; j++) o[i][j] *= sc;
        }
        #pragma unroll 8
        for (int kk = 0; kk < 64; kk++) {
            float a[4], bb[4];
            #pragma unroll
            for (int i = 0; i < 4; i++) a[i]  = Ps[(ty + 16*i)*68 + kk];
            #pragma unroll
            for (int j = 0; j < 4; j++) bb[j] = Vs[kk*68 + tx + 16*j];
            #pragma unroll
            for (int i = 0; i < 4; i++)
                #pragma unroll
                for (int j = 0; j < 4; j++)
                    o[i][j] = fmaf(a[i], bb[j], o[i][j]);
        }
        __syncthreads();
    }

    // normalize + write concat layout: O[b, q0+r, h*64 + c]
    #pragma unroll
    for (int i = 0; i < 4; i++) {
        const int r = ty + 16*i;
        const float inv = 1.f / rowl[r];
        #pragma unroll
        for (int j = 0; j < 4; j++) {
            const int c = tx + 16*j;
            O[((size_t)b * SEQ + q0 + r) * DIM + h * DK + c] = o[i][j] * inv;
        }
    }
}

// ---------------- LayerNorm over (S,D) per batch: 3 kernels (deterministic) ----
__global__ void ln_stats_kernel(const float* __restrict__ X,
                                float* __restrict__ psum, float* __restrict__ psq)
{
    const int b = blockIdx.y, chunk = blockIdx.x;   // 64 chunks of 4096
    const float* p = X + (size_t)b * SD + (size_t)chunk * 4096;
    float s = 0.f, q = 0.f;
    #pragma unroll
    for (int i = 0; i < 16; i++) {
        float v = p[threadIdx.x + 256*i];
        s += v; q += v*v;
    }
    #pragma unroll
    for (int off = 16; off; off >>= 1) {
        s += __shfl_down_sync(0xffffffffu, s, off);
        q += __shfl_down_sync(0xffffffffu, q, off);
    }
    __shared__ float ws[8], wq[8];
    if ((threadIdx.x & 31) == 0) { ws[threadIdx.x >> 5] = s; wq[threadIdx.x >> 5] = q; }
    __syncthreads();
    if (threadIdx.x == 0) {
        float S = 0.f, Q = 0.f;
        #pragma unroll
        for (int w = 0; w < 8; w++) { S += ws[w]; Q += wq[w]; }
        psum[b*64 + chunk] = S;
        psq [b*64 + chunk] = Q;
    }
}

__global__ void ln_final_kernel(const float* __restrict__ psum, const float* __restrict__ psq,
                                float* __restrict__ mean, float* __restrict__ rstd)
{
    const int b = blockIdx.x;
    float s = psum[b*64 + threadIdx.x];
    float q = psq [b*64 + threadIdx.x];
    #pragma unroll
    for (int off = 16; off; off >>= 1) {
        s += __shfl_down_sync(0xffffffffu, s, off);
        q += __shfl_down_sync(0xffffffffu, q, off);
    }
    __shared__ float ws[2], wq[2];
    if ((threadIdx.x & 31) == 0) { ws[threadIdx.x >> 5] = s; wq[threadIdx.x >> 5] = q; }
    __syncthreads();
    if (threadIdx.x == 0) {
        float S = ws[0] + ws[1], Q = wq[0] + wq[1];
        float m = S / (float)SD;
        float v = Q / (float)SD - m * m;
        mean[b] = m;
        rstd[b] = rsqrtf(v + LN_EPS);
    }
}

__global__ void ln_apply_kernel(const float* __restrict__ X,
                                const float* __restrict__ gamma, const float* __restrict__ beta,
                                const float* __restrict__ mean, const float* __restrict__ rstd,
                                float* __restrict__ Y)
{
    const float4* x4 = (const float4*)X;
    const float4* g4 = (const float4*)gamma;
    const float4* b4 = (const float4*)beta;
    float4* y4 = (float4*)Y;
    const int total = BATCH * (SD/4);   // 2097152
    for (int idx = blockIdx.x * blockDim.x + threadIdx.x; idx < total;
         idx += gridDim.x * blockDim.x) {
        const int b   = idx >> 16;          // SD/4 = 65536
        const int loc = idx & 65535;
        const float m = mean[b], r = rstd[b];
        float4 v = x4[idx], g = g4[loc], be = b4[loc];
        float4 out;
        out.x = (v.x - m) * r * g.x + be.x;
        out.y = (v.y - m) * r * g.y + be.y;
        out.z = (v.z - m) * r * g.z + be.z;
        out.w = (v.w - m) * r * g.w + be.w;
        y4[idx] = out;
    }
}

// ---------------- launch ------------------------------------------------------
static void run_ln(const float* in, const float* gamma, const float* beta, float* out,
                   float* psum, float* psq, float* mean, float* rstd)
{
    ln_stats_kernel<<<dim3(64, BATCH), 256>>>(in, psum, psq);
    ln_final_kernel<<<BATCH, 64>>>(psum, psq, mean, rstd);
    ln_apply_kernel<<<2048, 256>>>(in, gamma, beta, mean, rstd, out);
}

extern "C" void kernel_launch(void* const* d_in, const int* in_sizes, int n_in,
                              void* d_out, int out_size)
{
    const float* x     = (const float*)d_in[0];
    const float* Wq    = (const float*)d_in[1];
    const float* bq    = (const float*)d_in[2];
    const float* Wk    = (const float*)d_in[3];
    const float* bk    = (const float*)d_in[4];
    const float* Wv    = (const float*)d_in[5];
    const float* bv    = (const float*)d_in[6];
    const float* Wo    = (const float*)d_in[7];
    const float* bo    = (const float*)d_in[8];
    const float* W1    = (const float*)d_in[9];
    const float* b1    = (const float*)d_in[10];
    const float* W2    = (const float*)d_in[11];
    const float* b2    = (const float*)d_in[12];
    const float* W3    = (const float*)d_in[13];
    const float* b3    = (const float*)d_in[14];
    const float* gamma = (const float*)d_in[15];
    const float* beta  = (const float*)d_in[16];
    float* out = (float*)d_out;

    float *q_, *k_, *v_, *cc_, *y0_, *y1_, *z_, *y2_, *f1_, *f2_;
    float *psum_, *psq_, *mean_, *rstd_;
    cudaGetSymbolAddress((void**)&q_,  g_q);
    cudaGetSymbolAddress((void**)&k_,  g_k);
    cudaGetSymbolAddress((void**)&v_,  g_v);
    cudaGetSymbolAddress((void**)&cc_, g_cc);
    cudaGetSymbolAddress((void**)&y0_, g_y0);
    cudaGetSymbolAddress((void**)&y1_, g_y1);
    cudaGetSymbolAddress((void**)&z_,  g_z);
    cudaGetSymbolAddress((void**)&y2_, g_y2);
    cudaGetSymbolAddress((void**)&f1_, g_f1);
    cudaGetSymbolAddress((void**)&f2_, g_f2);
    cudaGetSymbolAddress((void**)&psum_, g_psum);
    cudaGetSymbolAddress((void**)&psq_,  g_psq);
    cudaGetSymbolAddress((void**)&mean_, g_mean);
    cudaGetSymbolAddress((void**)&rstd_, g_rstd);

    const int ATTN_SMEM = (4*64*68 + 64*16 + 3*64) * 4;
    cudaFuncSetAttribute(attn_kernel, cudaFuncAttributeMaxDynamicSharedMemorySize, ATTN_SMEM);

    const dim3 gemm_blk(256);
    // Q/K/V projections: [16384,512] x [512,512]^T + bias
    gemm_kernel<<<dim3(4, 128), gemm_blk>>>(x, Wq, bq, nullptr, q_, MTOT, DIM, DIM, 0);
    gemm_kernel<<<dim3(4, 128), gemm_blk>>>(x, Wk, bk, nullptr, k_, MTOT, DIM, DIM, 0);
    gemm_kernel<<<dim3(4, 128), gemm_blk>>>(x, Wv, bv, nullptr, v_, MTOT, DIM, DIM, 0);

    // attention -> concat
    attn_kernel<<<dim3(SEQ/64, BATCH*HEADS), 256, ATTN_SMEM>>>(q_, k_, v_, cc_);

    // output projection + bias + residual(x)
    gemm_kernel<<<dim3(4, 128), gemm_blk>>>(cc_, Wo, bo, x, y0_, MTOT, DIM, DIM, 0);

    // LN1
    run_ln(y0_, gamma, beta, y1_, psum_, psq_, mean_, rstd_);

    // FFN
    gemm_kernel<<<dim3(2, 128), gemm_blk>>>(y1_, W1, b1, nullptr, f1_, MTOT, FF, DIM, 1);
    gemm_kernel<<<dim3(2, 128), gemm_blk>>>(f1_, W2, b2, nullptr, f2_, MTOT, FF, FF, 1);
    gemm_kernel<<<dim3(4, 128), gemm_blk>>>(f2_, W3, b3, y1_, z_, MTOT, DIM, FF, 0);

    // LN2
    run_ln(z_, gamma, beta, y2_, psum_, psq_, mean_, rstd_);

    // LN3 (final) -> d_out
    run_ln(y2_, gamma, beta, out, psum_, psq_, mean_, rstd_);
}

// round 3
// speedup vs baseline: 1.8220x; 1.8220x over previous
#include <cuda_runtime.h>
#include <cuda_bf16.h>
#include <cstdint>
#include <cstdio>

// Problem constants
#define BATCH 32
#define SEQ   512
#define DIM   512
#define HEADS 8
#define DK    64
#define FF    200
#define MTOT  (BATCH*SEQ)        // 16384
#define SD    (SEQ*DIM)          // 262144
#define LN_EPS 1e-5f

// ---------------- scratch (device globals; no allocation allowed) -------------
__device__ float g_q [MTOT*DIM];
__device__ float g_k [MTOT*DIM];
__device__ float g_v [MTOT*DIM];
__device__ float g_cc[MTOT*DIM];
__device__ float g_y0[MTOT*DIM];
__device__ float g_y1[MTOT*DIM];
__device__ float g_z [MTOT*DIM];
__device__ float g_y2[MTOT*DIM];
__device__ float g_f1[MTOT*FF];
__device__ float g_f2[MTOT*FF];
__device__ float g_psum[BATCH*64];
__device__ float g_psq [BATCH*64];
__device__ float g_mean[BATCH];
__device__ float g_rstd[BATCH];

// ---------------- tf32 helpers ------------------------------------------------
__device__ __forceinline__ float to_tf32(float x) {
    uint32_t u;
    asm("cvt.rna.tf32.f32 %0, %1;" : "=r"(u) : "f"(x));
    return __uint_as_float(u);
}

__device__ __forceinline__ void mma_tf32(float* c, const uint32_t* a, const uint32_t* b) {
    asm volatile(
        "mma.sync.aligned.m16n8k8.row.col.f32.tf32.tf32.f32 "
        "{%0,%1,%2,%3}, {%4,%5,%6,%7}, {%8,%9}, {%0,%1,%2,%3};\n"
        : "+f"(c[0]), "+f"(c[1]), "+f"(c[2]), "+f"(c[3])
        : "r"(a[0]), "r"(a[1]), "r"(a[2]), "r"(a[3]),
          "r"(b[0]), "r"(b[1]));
}

// ---------------- TF32 tensor-core GEMM: C[M,N] = A[M,K]*B[N,K]^T + bias (+res)(relu)
// block tile 128x128, BK=32, 256 threads = 8 warps (2x4), warp tile 64x32
__global__ void __launch_bounds__(256)
gemm_tf32_kernel(const float* __restrict__ A, const float* __restrict__ B,
                 const float* __restrict__ bias, const float* __restrict__ res,
                 float* __restrict__ C, int M, int N, int K, int relu)
{
    __shared__ float As[128][36];   // [m][k], pitch 36 (conflict-free frags + stores)
    __shared__ float Bs[128][36];   // [n][k]

    const int tid  = threadIdx.x;
    const int wid  = tid >> 5;
    const int lane = tid & 31;
    const int wm   = wid >> 2;          // 0..1
    const int wn   = wid & 3;           // 0..3
    const int qr   = lane >> 2;         // 0..7 groupID
    const int qc   = lane & 3;          // 0..3 thread-in-group
    const int m0   = blockIdx.y * 128;
    const int n0   = blockIdx.x * 128;

    const int lr  = tid >> 3;           // 0..31 (row within 32-row chunk)
    const int lc4 = (tid & 7) * 4;      // 0..28 (k col chunk)

    float acc[4][4][4];
    #pragma unroll
    for (int i = 0; i < 4; i++)
        #pragma unroll
        for (int j = 0; j < 4; j++)
            #pragma unroll
            for (int r = 0; r < 4; r++) acc[i][j][r] = 0.f;

    for (int k0 = 0; k0 < K; k0 += 32) {
        const int kc = k0 + lc4;
        // load A tile (128x32) and B tile (128x32), tf32-rounded
        #pragma unroll
        for (int i = 0; i < 4; i++) {
            const int r = lr + i * 32;
            float4 av = make_float4(0.f, 0.f, 0.f, 0.f);
            if (kc < K) av = *(const float4*)(A + (size_t)(m0 + r) * K + kc);
            As[r][lc4+0] = to_tf32(av.x); As[r][lc4+1] = to_tf32(av.y);
            As[r][lc4+2] = to_tf32(av.z); As[r][lc4+3] = to_tf32(av.w);

            const int n = n0 + r;
            float4 bv = make_float4(0.f, 0.f, 0.f, 0.f);
            if (n < N && kc < K) bv = *(const float4*)(B + (size_t)n * K + kc);
            Bs[r][lc4+0] = to_tf32(bv.x); Bs[r][lc4+1] = to_tf32(bv.y);
            Bs[r][lc4+2] = to_tf32(bv.z); Bs[r][lc4+3] = to_tf32(bv.w);
        }
        __syncthreads();

        #pragma unroll
        for (int ks = 0; ks < 32; ks += 8) {
            uint32_t afr[4][4], bfr[4][2];
            #pragma unroll
            for (int i = 0; i < 4; i++) {
                const int mb = wm * 64 + i * 16 + qr;
                afr[i][0] = __float_as_uint(As[mb    ][ks + qc    ]);
                afr[i][1] = __float_as_uint(As[mb + 8][ks + qc    ]);
                afr[i][2] = __float_as_uint(As[mb    ][ks + qc + 4]);
                afr[i][3] = __float_as_uint(As[mb + 8][ks + qc + 4]);
            }
            #pragma unroll
            for (int j = 0; j < 4; j++) {
                const int nb = wn * 32 + j * 8 + qr;
                bfr[j][0] = __float_as_uint(Bs[nb][ks + qc    ]);
                bfr[j][1] = __float_as_uint(Bs[nb][ks + qc + 4]);
            }
            #pragma unroll
            for (int i = 0; i < 4; i++)
                #pragma unroll
                for (int j = 0; j < 4; j++)
                    mma_tf32(acc[i][j], afr[i], bfr[j]);
        }
        __syncthreads();
    }

    // epilogue: c0,c1 at (row, col..col+1); c2,c3 at (row+8, ...)
    #pragma unroll
    for (int i = 0; i < 4; i++) {
        const int row = m0 + wm * 64 + i * 16 + qr;
        #pragma unroll
        for (int j = 0; j < 4; j++) {
            const int col = n0 + wn * 32 + j * 8 + 2 * qc;
            if (col < N) {
                const float2 bi = *(const float2*)(bias + col);
                float v0 = acc[i][j][0] + bi.x;
                float v1 = acc[i][j][1] + bi.y;
                float v2 = acc[i][j][2] + bi.x;
                float v3 = acc[i][j][3] + bi.y;
                if (res) {
                    const float2 r0 = *(const float2*)(res + (size_t)row * N + col);
                    const float2 r1 = *(const float2*)(res + (size_t)(row + 8) * N + col);
                    v0 += r0.x; v1 += r0.y; v2 += r1.x; v3 += r1.y;
                }
                if (relu) {
                    v0 = fmaxf(v0, 0.f); v1 = fmaxf(v1, 0.f);
                    v2 = fmaxf(v2, 0.f); v3 = fmaxf(v3, 0.f);
                }
                *(float2*)(C + (size_t)row * N + col)       = make_float2(v0, v1);
                *(float2*)(C + (size_t)(row + 8) * N + col) = make_float2(v2, v3);
            }
        }
    }
}

// ---------------- fused attention: per (b,h) x 64-query tile, online softmax ---
// grid (S/64, B*H), 256 threads. smem: Qs,KsT,Vs,Ps [64][68] + red[64][16] + stats.
__global__ void attn_kernel(const float* __restrict__ Q, const float* __restrict__ Kp,
                            const float* __restrict__ Vp, float* __restrict__ O)
{
    extern __shared__ float sm[];
    float* Qs   = sm;                // [64][68] row=q, col=dk
    float* KsT  = sm + 64*68;        // [64][68] row=dk, col=t
    float* Vs   = sm + 2*64*68;      // [64][68] row=t, col=dk
    float* Ps   = sm + 3*64*68;      // [64][68] row=q, col=t
    float* red  = sm + 4*64*68;      // [64][16]
    float* rowm = red + 64*16;
    float* rowl = rowm + 64;
    float* rowsc= rowl + 64;

    const int tid = threadIdx.x;
    const int tx = tid & 15, ty = tid >> 4;
    const int bh = blockIdx.y;
    const int b  = bh >> 3, h = bh & 7;
    const int q0 = blockIdx.x * 64;
    const size_t baseQ = ((size_t)b * SEQ + q0) * DIM + h * DK;
    const size_t baseK = ((size_t)b * SEQ) * DIM + h * DK;
    const int lr = tid >> 2;         // 0..63 (row)
    const int lc = (tid & 3) * 4;    // 0,4,8,12 (col chunk base)

    // load Q tile once: each thread covers columns lc + 16*i, i=0..3 (16 floats)
    #pragma unroll
    for (int i = 0; i < 4; i++) {
        const int c = lc + 16 * i;
        float4 qv = *(const float4*)(Q + baseQ + (size_t)lr * DIM + c);
        Qs[lr*68 + c + 0] = qv.x; Qs[lr*68 + c + 1] = qv.y;
        Qs[lr*68 + c + 2] = qv.z; Qs[lr*68 + c + 3] = qv.w;
    }
    if (tid < 64) { rowm[tid] = -1e30f; rowl[tid] = 0.f; }

    float o[4][4];
    #pragma unroll
    for (int i = 0; i < 4; i++)
        #pragma unroll
        for (int j = 0; j < 4; j++) o[i][j] = 0.f;

    __syncthreads();

    for (int kt = 0; kt < SEQ/64; kt++) {
        const int t0 = kt * 64;
        // load K (transposed store) and V; full 64x64 coverage per tile
        #pragma unroll
        for (int i = 0; i < 4; i++) {
            const int c = lc + 16 * i;
            float4 kv = *(const float4*)(Kp + baseK + (size_t)(t0 + lr) * DIM + c);
            KsT[(c+0)*68 + lr] = kv.x; KsT[(c+1)*68 + lr] = kv.y;
            KsT[(c+2)*68 + lr] = kv.z; KsT[(c+3)*68 + lr] = kv.w;
            float4 vv = *(const float4*)(Vp + baseK + (size_t)(t0 + lr) * DIM + c);
            Vs[lr*68 + c + 0] = vv.x; Vs[lr*68 + c + 1] = vv.y;
            Vs[lr*68 + c + 2] = vv.z; Vs[lr*68 + c + 3] = vv.w;
        }
        __syncthreads();

        // S = Q * K^T * scale
        float s[4][4];
        #pragma unroll
        for (int i = 0; i < 4; i++)
            #pragma unroll
            for (int j = 0; j < 4; j++) s[i][j] = 0.f;
        #pragma unroll 8
        for (int kk = 0; kk < 64; kk++) {
            float a[4], bb[4];
            #pragma unroll
            for (int i = 0; i < 4; i++) a[i]  = Qs[(ty + 16*i)*68 + kk];
            #pragma unroll
            for (int j = 0; j < 4; j++) bb[j] = KsT[kk*68 + tx + 16*j];
            #pragma unroll
            for (int i = 0; i < 4; i++)
                #pragma unroll
                for (int j = 0; j < 4; j++)
                    s[i][j] = fmaf(a[i], bb[j], s[i][j]);
        }
        #pragma unroll
        for (int i = 0; i < 4; i++)
            #pragma unroll
            for (int j = 0; j < 4; j++) s[i][j] *= 0.125f;

        // tile row max -> red
        #pragma unroll
        for (int i = 0; i < 4; i++) {
            float m01 = fmaxf(s[i][0], s[i][1]);
            float m23 = fmaxf(s[i][2], s[i][3]);
            red[(ty + 16*i)*16 + tx] = fmaxf(m01, m23);
        }
        __syncthreads();
        if (tid < 64) {
            float mo = rowm[tid], mn = mo;
            #pragma unroll
            for (int t = 0; t < 16; t++) mn = fmaxf(mn, red[tid*16 + t]);
            rowsc[tid] = __expf(mo - mn);
            rowm[tid]  = mn;
        }
        __syncthreads();

        // P = exp(S - m), partial row sums
        #pragma unroll
        for (int i = 0; i < 4; i++) {
            const int r = ty + 16*i;
            const float mn = rowm[r];
            float rs = 0.f;
            #pragma unroll
            for (int j = 0; j < 4; j++) {
                float p = __expf(s[i][j] - mn);
                Ps[r*68 + tx + 16*j] = p;
                rs += p;
            }
            red[r*16 + tx] = rs;
        }
        __syncthreads();
        if (tid < 64) {
            float ssum = 0.f;
            #pragma unroll
            for (int t = 0; t < 16; t++) ssum += red[tid*16 + t];
            rowl[tid] = rowl[tid] * rowsc[tid] + ssum;
        }

        // O = O*scale + P*V
        #pragma unroll
        for (int i = 0; i < 4; i++) {
            const float sc = rowsc[ty + 16*i];
            #pragma unroll
            for (int j = 0; j < 4; j++) o[i][j] *= sc;
        }
        #pragma unroll 8
        for (int kk = 0; kk < 64; kk++) {
            float a[4], bb[4];
            #pragma unroll
            for (int i = 0; i < 4; i++) a[i]  = Ps[(ty + 16*i)*68 + kk];
            #pragma unroll
            for (int j = 0; j < 4; j++) bb[j] = Vs[kk*68 + tx + 16*j];
            #pragma unroll
            for (int i = 0; i < 4; i++)
                #pragma unroll
                for (int j = 0; j < 4; j++)
                    o[i][j] = fmaf(a[i], bb[j], o[i][j]);
        }
        __syncthreads();
    }

    // normalize + write concat layout: O[b, q0+r, h*64 + c]
    #pragma unroll
    for (int i = 0; i < 4; i++) {
        const int r = ty + 16*i;
        const float inv = 1.f / rowl[r];
        #pragma unroll
        for (int j = 0; j < 4; j++) {
            const int c = tx + 16*j;
            O[((size_t)b * SEQ + q0 + r) * DIM + h * DK + c] = o[i][j] * inv;
        }
    }
}

// ---------------- LayerNorm over (S,D) per batch: 3 kernels (deterministic) ----
__global__ void ln_stats_kernel(const float* __restrict__ X,
                                float* __restrict__ psum, float* __restrict__ psq)
{
    const int b = blockIdx.y, chunk = blockIdx.x;   // 64 chunks of 4096
    const float* p = X + (size_t)b * SD + (size_t)chunk * 4096;
    float s = 0.f, q = 0.f;
    #pragma unroll
    for (int i = 0; i < 16; i++) {
        float v = p[threadIdx.x + 256*i];
        s += v; q += v*v;
    }
    #pragma unroll
    for (int off = 16; off; off >>= 1) {
        s += __shfl_down_sync(0xffffffffu, s, off);
        q += __shfl_down_sync(0xffffffffu, q, off);
    }
    __shared__ float ws[8], wq[8];
    if ((threadIdx.x & 31) == 0) { ws[threadIdx.x >> 5] = s; wq[threadIdx.x >> 5] = q; }
    __syncthreads();
    if (threadIdx.x == 0) {
        float S = 0.f, Q = 0.f;
        #pragma unroll
        for (int w = 0; w < 8; w++) { S += ws[w]; Q += wq[w]; }
        psum[b*64 + chunk] = S;
        psq [b*64 + chunk] = Q;
    }
}

__global__ void ln_final_kernel(const float* __restrict__ psum, const float* __restrict__ psq,
                                float* __restrict__ mean, float* __restrict__ rstd)
{
    const int b = blockIdx.x;
    float s = psum[b*64 + threadIdx.x];
    float q = psq [b*64 + threadIdx.x];
    #pragma unroll
    for (int off = 16; off; off >>= 1) {
        s += __shfl_down_sync(0xffffffffu, s, off);
        q += __shfl_down_sync(0xffffffffu, q, off);
    }
    __shared__ float ws[2], wq[2];
    if ((threadIdx.x & 31) == 0) { ws[threadIdx.x >> 5] = s; wq[threadIdx.x >> 5] = q; }
    __syncthreads();
    if (threadIdx.x == 0) {
        float S = ws[0] + ws[1], Q = wq[0] + wq[1];
        float m = S / (float)SD;
        float v = Q / (float)SD - m * m;
        mean[b] = m;
        rstd[b] = rsqrtf(v + LN_EPS);
    }
}

__global__ void ln_apply_kernel(const float* __restrict__ X,
                                const float* __restrict__ gamma, const float* __restrict__ beta,
                                const float* __restrict__ mean, const float* __restrict__ rstd,
                                float* __restrict__ Y)
{
    const float4* x4 = (const float4*)X;
    const float4* g4 = (const float4*)gamma;
    const float4* b4 = (const float4*)beta;
    float4* y4 = (float4*)Y;
    const int total = BATCH * (SD/4);   // 2097152
    for (int idx = blockIdx.x * blockDim.x + threadIdx.x; idx < total;
         idx += gridDim.x * blockDim.x) {
        const int b   = idx >> 16;          // SD/4 = 65536
        const int loc = idx & 65535;
        const float m = mean[b], r = rstd[b];
        float4 v = x4[idx], g = g4[loc], be = b4[loc];
        float4 out;
        out.x = (v.x - m) * r * g.x + be.x;
        out.y = (v.y - m) * r * g.y + be.y;
        out.z = (v.z - m) * r * g.z + be.z;
        out.w = (v.w - m) * r * g.w + be.w;
        y4[idx] = out;
    }
}

// ---------------- launch ------------------------------------------------------
static void run_ln(const float* in, const float* gamma, const float* beta, float* out,
                   float* psum, float* psq, float* mean, float* rstd)
{
    ln_stats_kernel<<<dim3(64, BATCH), 256>>>(in, psum, psq);
    ln_final_kernel<<<BATCH, 64>>>(psum, psq, mean, rstd);
    ln_apply_kernel<<<2048, 256>>>(in, gamma, beta, mean, rstd, out);
}

extern "C" void kernel_launch(void* const* d_in, const int* in_sizes, int n_in,
                              void* d_out, int out_size)
{
    const float* x     = (const float*)d_in[0];
    const float* Wq    = (const float*)d_in[1];
    const float* bq    = (const float*)d_in[2];
    const float* Wk    = (const float*)d_in[3];
    const float* bk    = (const float*)d_in[4];
    const float* Wv    = (const float*)d_in[5];
    const float* bv    = (const float*)d_in[6];
    const float* Wo    = (const float*)d_in[7];
    const float* bo    = (const float*)d_in[8];
    const float* W1    = (const float*)d_in[9];
    const float* b1    = (const float*)d_in[10];
    const float* W2    = (const float*)d_in[11];
    const float* b2    = (const float*)d_in[12];
    const float* W3    = (const float*)d_in[13];
    const float* b3    = (const float*)d_in[14];
    const float* gamma = (const float*)d_in[15];
    const float* beta  = (const float*)d_in[16];
    float* out = (float*)d_out;

    float *q_, *k_, *v_, *cc_, *y0_, *y1_, *z_, *y2_, *f1_, *f2_;
    float *psum_, *psq_, *mean_, *rstd_;
    cudaGetSymbolAddress((void**)&q_,  g_q);
    cudaGetSymbolAddress((void**)&k_,  g_k);
    cudaGetSymbolAddress((void**)&v_,  g_v);
    cudaGetSymbolAddress((void**)&cc_, g_cc);
    cudaGetSymbolAddress((void**)&y0_, g_y0);
    cudaGetSymbolAddress((void**)&y1_, g_y1);
    cudaGetSymbolAddress((void**)&z_,  g_z);
    cudaGetSymbolAddress((void**)&y2_, g_y2);
    cudaGetSymbolAddress((void**)&f1_, g_f1);
    cudaGetSymbolAddress((void**)&f2_, g_f2);
    cudaGetSymbolAddress((void**)&psum_, g_psum);
    cudaGetSymbolAddress((void**)&psq_,  g_psq);
    cudaGetSymbolAddress((void**)&mean_, g_mean);
    cudaGetSymbolAddress((void**)&rstd_, g_rstd);

    const int ATTN_SMEM = (4*64*68 + 64*16 + 3*64) * 4;
    cudaFuncSetAttribute(attn_kernel, cudaFuncAttributeMaxDynamicSharedMemorySize, ATTN_SMEM);

    // Q/K/V projections: [16384,512] x [512,512]^T + bias  (TF32 tensor cores)
    gemm_tf32_kernel<<<dim3(4, 128), 256>>>(x, Wq, bq, nullptr, q_, MTOT, DIM, DIM, 0);
    gemm_tf32_kernel<<<dim3(4, 128), 256>>>(x, Wk, bk, nullptr, k_, MTOT, DIM, DIM, 0);
    gemm_tf32_kernel<<<dim3(4, 128), 256>>>(x, Wv, bv, nullptr, v_, MTOT, DIM, DIM, 0);

    // attention -> concat
    attn_kernel<<<dim3(SEQ/64, BATCH*HEADS), 256, ATTN_SMEM>>>(q_, k_, v_, cc_);

    // output projection + bias + residual(x)
    gemm_tf32_kernel<<<dim3(4, 128), 256>>>(cc_, Wo, bo, x, y0_, MTOT, DIM, DIM, 0);

    // LN1
    run_ln(y0_, gamma, beta, y1_, psum_, psq_, mean_, rstd_);

    // FFN
    gemm_tf32_kernel<<<dim3(2, 128), 256>>>(y1_, W1, b1, nullptr, f1_, MTOT, FF, DIM, 1);
    gemm_tf32_kernel<<<dim3(2, 128), 256>>>(f1_, W2, b2, nullptr, f2_, MTOT, FF, FF, 1);
    gemm_tf32_kernel<<<dim3(4, 128), 256>>>(f2_, W3, b3, y1_, z_, MTOT, DIM, FF, 0);

    // LN2
    run_ln(z_, gamma, beta, y2_, psum_, psq_, mean_, rstd_);

    // LN3 (final) -> d_out
    run_ln(y2_, gamma, beta, out, psum_, psq_, mean_, rstd_);
}

// round 4
// speedup vs baseline: 2.6652x; 1.4628x over previous
#include <cuda_runtime.h>
#include <cuda_bf16.h>
#include <cstdint>
#include <cstdio>

// Problem constants
#define BATCH 32
#define SEQ   512
#define DIM   512
#define HEADS 8
#define DK    64
#define FF    200
#define MTOT  (BATCH*SEQ)        // 16384
#define SD    (SEQ*DIM)          // 262144
#define LN_EPS 1e-5f

// ---------------- scratch (device globals; no allocation allowed) -------------
__device__ float g_q [MTOT*DIM];
__device__ float g_k [MTOT*DIM];
__device__ float g_v [MTOT*DIM];
__device__ float g_cc[MTOT*DIM];
__device__ float g_y0[MTOT*DIM];
__device__ float g_y1[MTOT*DIM];
__device__ float g_z [MTOT*DIM];
__device__ float g_y2[MTOT*DIM];
__device__ float g_f1[MTOT*FF];
__device__ float g_f2[MTOT*FF];
__device__ float g_psum[BATCH*64];
__device__ float g_psq [BATCH*64];
__device__ float g_mean[BATCH];
__device__ float g_rstd[BATCH];

// ---------------- tf32 helpers ------------------------------------------------
__device__ __forceinline__ float to_tf32(float x) {
    uint32_t u;
    asm("cvt.rna.tf32.f32 %0, %1;" : "=r"(u) : "f"(x));
    return __uint_as_float(u);
}

__device__ __forceinline__ void mma_tf32(float* c, const uint32_t* a, const uint32_t* b) {
    asm volatile(
        "mma.sync.aligned.m16n8k8.row.col.f32.tf32.tf32.f32 "
        "{%0,%1,%2,%3}, {%4,%5,%6,%7}, {%8,%9}, {%0,%1,%2,%3};\n"
        : "+f"(c[0]), "+f"(c[1]), "+f"(c[2]), "+f"(c[3])
        : "r"(a[0]), "r"(a[1]), "r"(a[2]), "r"(a[3]),
          "r"(b[0]), "r"(b[1]));
}

// ---------------- TF32 tensor-core GEMM: C[M,N] = A[M,K]*B[N,K]^T + bias (+res)(relu)
// block tile 128x128, BK=32, 256 threads = 8 warps (2x4), warp tile 64x32
__global__ void __launch_bounds__(256)
gemm_tf32_kernel(const float* __restrict__ A, const float* __restrict__ B,
                 const float* __restrict__ bias, const float* __restrict__ res,
                 float* __restrict__ C, int M, int N, int K, int relu)
{
    __shared__ float As[128][36];   // [m][k], pitch 36 (conflict-free frags + stores)
    __shared__ float Bs[128][36];   // [n][k]

    const int tid  = threadIdx.x;
    const int wid  = tid >> 5;
    const int lane = tid & 31;
    const int wm   = wid >> 2;          // 0..1
    const int wn   = wid & 3;           // 0..3
    const int qr   = lane >> 2;         // 0..7 groupID
    const int qc   = lane & 3;          // 0..3 thread-in-group
    const int m0   = blockIdx.y * 128;
    const int n0   = blockIdx.x * 128;

    const int lr  = tid >> 3;           // 0..31 (row within 32-row chunk)
    const int lc4 = (tid & 7) * 4;      // 0..28 (k col chunk)

    float acc[4][4][4];
    #pragma unroll
    for (int i = 0; i < 4; i++)
        #pragma unroll
        for (int j = 0; j < 4; j++)
            #pragma unroll
            for (int r = 0; r < 4; r++) acc[i][j][r] = 0.f;

    for (int k0 = 0; k0 < K; k0 += 32) {
        const int kc = k0 + lc4;
        // load A tile (128x32) and B tile (128x32), tf32-rounded
        #pragma unroll
        for (int i = 0; i < 4; i++) {
            const int r = lr + i * 32;
            float4 av = make_float4(0.f, 0.f, 0.f, 0.f);
            if (kc < K) av = *(const float4*)(A + (size_t)(m0 + r) * K + kc);
            As[r][lc4+0] = to_tf32(av.x); As[r][lc4+1] = to_tf32(av.y);
            As[r][lc4+2] = to_tf32(av.z); As[r][lc4+3] = to_tf32(av.w);

            const int n = n0 + r;
            float4 bv = make_float4(0.f, 0.f, 0.f, 0.f);
            if (n < N && kc < K) bv = *(const float4*)(B + (size_t)n * K + kc);
            Bs[r][lc4+0] = to_tf32(bv.x); Bs[r][lc4+1] = to_tf32(bv.y);
            Bs[r][lc4+2] = to_tf32(bv.z); Bs[r][lc4+3] = to_tf32(bv.w);
        }
        __syncthreads();

        #pragma unroll
        for (int ks = 0; ks < 32; ks += 8) {
            uint32_t afr[4][4], bfr[4][2];
            #pragma unroll
            for (int i = 0; i < 4; i++) {
                const int mb = wm * 64 + i * 16 + qr;
                afr[i][0] = __float_as_uint(As[mb    ][ks + qc    ]);
                afr[i][1] = __float_as_uint(As[mb + 8][ks + qc    ]);
                afr[i][2] = __float_as_uint(As[mb    ][ks + qc + 4]);
                afr[i][3] = __float_as_uint(As[mb + 8][ks + qc + 4]);
            }
            #pragma unroll
            for (int j = 0; j < 4; j++) {
                const int nb = wn * 32 + j * 8 + qr;
                bfr[j][0] = __float_as_uint(Bs[nb][ks + qc    ]);
                bfr[j][1] = __float_as_uint(Bs[nb][ks + qc + 4]);
            }
            #pragma unroll
            for (int i = 0; i < 4; i++)
                #pragma unroll
                for (int j = 0; j < 4; j++)
                    mma_tf32(acc[i][j], afr[i], bfr[j]);
        }
        __syncthreads();
    }

    // epilogue: c0,c1 at (row, col..col+1); c2,c3 at (row+8, ...)
    #pragma unroll
    for (int i = 0; i < 4; i++) {
        const int row = m0 + wm * 64 + i * 16 + qr;
        #pragma unroll
        for (int j = 0; j < 4; j++) {
            const int col = n0 + wn * 32 + j * 8 + 2 * qc;
            if (col < N) {
                const float2 bi = *(const float2*)(bias + col);
                float v0 = acc[i][j][0] + bi.x;
                float v1 = acc[i][j][1] + bi.y;
                float v2 = acc[i][j][2] + bi.x;
                float v3 = acc[i][j][3] + bi.y;
                if (res) {
                    const float2 r0 = *(const float2*)(res + (size_t)row * N + col);
                    const float2 r1 = *(const float2*)(res + (size_t)(row + 8) * N + col);
                    v0 += r0.x; v1 += r0.y; v2 += r1.x; v3 += r1.y;
                }
                if (relu) {
                    v0 = fmaxf(v0, 0.f); v1 = fmaxf(v1, 0.f);
                    v2 = fmaxf(v2, 0.f); v3 = fmaxf(v3, 0.f);
                }
                *(float2*)(C + (size_t)row * N + col)       = make_float2(v0, v1);
                *(float2*)(C + (size_t)(row + 8) * N + col) = make_float2(v2, v3);
            }
        }
    }
}

// ---------------- TF32 tensor-core flash attention ---------------------------
// grid (SEQ/64, BATCH*HEADS), 128 threads = 4 warps; warp owns 16 query rows.
// smem tiles pitch 68 -> fragment LDS bank = 4*qr+qc (conflict-free).
#define AP 68
__global__ void __launch_bounds__(128)
attn_mma_kernel(const float* __restrict__ Q, const float* __restrict__ K,
                const float* __restrict__ V, float* __restrict__ O)
{
    extern __shared__ float sm[];
    float (*Qs)[AP] = (float(*)[AP])sm;              // [64][AP]  row=q,  col=dk
    float (*Ks)[AP] = (float(*)[AP])(sm + 64*AP);    // [64][AP]  row=t,  col=dk
    float (*Vt)[AP] = (float(*)[AP])(sm + 2*64*AP);  // [64][AP]  row=dk, col=t
    float (*Ps)[AP] = (float(*)[AP])(sm + 3*64*AP);  // [64][AP]  row=q,  col=t

    const int tid  = threadIdx.x;
    const int w    = tid >> 5;
    const int lane = tid & 31;
    const int qr   = lane >> 2;     // 0..7
    const int qc   = lane & 3;      // 0..3
    const int bh   = blockIdx.y;
    const int b    = bh >> 3, h = bh & 7;
    const int q0   = blockIdx.x * 64;
    const size_t baseQ = ((size_t)b * SEQ + q0) * DIM + h * DK;
    const size_t baseK = ((size_t)b * SEQ) * DIM + h * DK;
    const int mb = w * 16;

    // load Q tile (64x64), coalesced: 16 lanes cover a full row
    #pragma unroll
    for (int it = 0; it < 8; it++) {
        const int idx = tid + 128 * it;
        const int r = idx >> 4, c4 = (idx & 15) * 4;
        float4 v = *(const float4*)(Q + baseQ + (size_t)r * DIM + c4);
        Qs[r][c4+0] = to_tf32(v.x); Qs[r][c4+1] = to_tf32(v.y);
        Qs[r][c4+2] = to_tf32(v.z); Qs[r][c4+3] = to_tf32(v.w);
    }

    float o[8][4];
    #pragma unroll
    for (int j = 0; j < 8; j++)
        #pragma unroll
        for (int r = 0; r < 4; r++) o[j][r] = 0.f;
    float rowm0 = -1e30f, rowm1 = -1e30f, rowl0 = 0.f, rowl1 = 0.f;

    __syncthreads();

    for (int kt = 0; kt < SEQ / 64; kt++) {
        const int t0 = kt * 64;
        // load K tile [t][dk] and V tile transposed [dk][t]
        #pragma unroll
        for (int it = 0; it < 8; it++) {
            const int idx = tid + 128 * it;
            const int r = idx >> 4, c4 = (idx & 15) * 4;
            float4 kv = *(const float4*)(K + baseK + (size_t)(t0 + r) * DIM + c4);
            Ks[r][c4+0] = to_tf32(kv.x); Ks[r][c4+1] = to_tf32(kv.y);
            Ks[r][c4+2] = to_tf32(kv.z); Ks[r][c4+3] = to_tf32(kv.w);
            float4 vv = *(const float4*)(V + baseK + (size_t)(t0 + r) * DIM + c4);
            Vt[c4+0][r] = to_tf32(vv.x); Vt[c4+1][r] = to_tf32(vv.y);
            Vt[c4+2][r] = to_tf32(vv.z); Vt[c4+3][r] = to_tf32(vv.w);
        }
        __syncthreads();

        // S = Q * K^T  (warp rows mb..mb+15, all 64 key cols)
        float s[8][4];
        #pragma unroll
        for (int j = 0; j < 8; j++)
            #pragma unroll
            for (int r = 0; r < 4; r++) s[j][r] = 0.f;
        #pragma unroll
        for (int ks = 0; ks < 64; ks += 8) {
            uint32_t a[4];
            a[0] = __float_as_uint(Qs[mb + qr    ][ks + qc    ]);
            a[1] = __float_as_uint(Qs[mb + qr + 8][ks + qc    ]);
            a[2] = __float_as_uint(Qs[mb + qr    ][ks + qc + 4]);
            a[3] = __float_as_uint(Qs[mb + qr + 8][ks + qc + 4]);
            #pragma unroll
            for (int j = 0; j < 8; j++) {
                uint32_t bf[2];
                bf[0] = __float_as_uint(Ks[j*8 + qr][ks + qc    ]);
                bf[1] = __float_as_uint(Ks[j*8 + qr][ks + qc + 4]);
                mma_tf32(s[j], a, bf);
            }
        }

        // scale + tile row max (rows qr -> half0, qr+8 -> half1)
        float mt0 = -1e30f, mt1 = -1e30f;
        #pragma unroll
        for (int j = 0; j < 8; j++) {
            s[j][0] *= 0.125f; s[j][1] *= 0.125f;
            s[j][2] *= 0.125f; s[j][3] *= 0.125f;
            mt0 = fmaxf(mt0, fmaxf(s[j][0], s[j][1]));
            mt1 = fmaxf(mt1, fmaxf(s[j][2], s[j][3]));
        }
        mt0 = fmaxf(mt0, __shfl_xor_sync(0xffffffffu, mt0, 1));
        mt0 = fmaxf(mt0, __shfl_xor_sync(0xffffffffu, mt0, 2));
        mt1 = fmaxf(mt1, __shfl_xor_sync(0xffffffffu, mt1, 1));
        mt1 = fmaxf(mt1, __shfl_xor_sync(0xffffffffu, mt1, 2));

        const float mn0 = fmaxf(rowm0, mt0), mn1 = fmaxf(rowm1, mt1);
        const float sc0 = __expf(rowm0 - mn0), sc1 = __expf(rowm1 - mn1);
        rowm0 = mn0; rowm1 = mn1;

        // P = exp(S - m) -> smem (A-operand layout), partial row sums
        float ps0 = 0.f, ps1 = 0.f;
        #pragma unroll
        for (int j = 0; j < 8; j++) {
            const float p0 = __expf(s[j][0] - mn0);
            const float p1 = __expf(s[j][1] - mn0);
            const float p2 = __expf(s[j][2] - mn1);
            const float p3 = __expf(s[j][3] - mn1);
            ps0 += p0 + p1; ps1 += p2 + p3;
            const int col = j * 8 + 2 * qc;
            Ps[mb + qr    ][col] = to_tf32(p0); Ps[mb + qr    ][col+1] = to_tf32(p1);
            Ps[mb + qr + 8][col] = to_tf32(p2); Ps[mb + qr + 8][col+1] = to_tf32(p3);
        }
        ps0 += __shfl_xor_sync(0xffffffffu, ps0, 1);
        ps0 += __shfl_xor_sync(0xffffffffu, ps0, 2);
        ps1 += __shfl_xor_sync(0xffffffffu, ps1, 1);
        ps1 += __shfl_xor_sync(0xffffffffu, ps1, 2);
        rowl0 = rowl0 * sc0 + ps0;
        rowl1 = rowl1 * sc1 + ps1;

        // rescale O accumulator
        #pragma unroll
        for (int j = 0; j < 8; j++) {
            o[j][0] *= sc0; o[j][1] *= sc0;
            o[j][2] *= sc1; o[j][3] *= sc1;
        }
        __syncwarp();

        // O += P * V   (B operand = Vt[dk][t])
        #pragma unroll
        for (int ks = 0; ks < 64; ks += 8) {
            uint32_t a[4];
            a[0] = __float_as_uint(Ps[mb + qr    ][ks + qc    ]);
            a[1] = __float_as_uint(Ps[mb + qr + 8][ks + qc    ]);
            a[2] = __float_as_uint(Ps[mb + qr    ][ks + qc + 4]);
            a[3] = __float_as_uint(Ps[mb + qr + 8][ks + qc + 4]);
            #pragma unroll
            for (int j = 0; j < 8; j++) {
                uint32_t bf[2];
                bf[0] = __float_as_uint(Vt[j*8 + qr][ks + qc    ]);
                bf[1] = __float_as_uint(Vt[j*8 + qr][ks + qc + 4]);
                mma_tf32(o[j], a, bf);
            }
        }
        __syncthreads();
    }

    // normalize + write concat layout
    const float inv0 = 1.f / rowl0, inv1 = 1.f / rowl1;
    const int r0 = q0 + mb + qr, r1 = r0 + 8;
    #pragma unroll
    for (int j = 0; j < 8; j++) {
        const int col = h * DK + j * 8 + 2 * qc;
        *(float2*)(O + ((size_t)b * SEQ + r0) * DIM + col) =
            make_float2(o[j][0] * inv0, o[j][1] * inv0);
        *(float2*)(O + ((size_t)b * SEQ + r1) * DIM + col) =
            make_float2(o[j][2] * inv1, o[j][3] * inv1);
    }
}

// ---------------- LayerNorm over (S,D) per batch: 3 kernels (deterministic) ----
__global__ void ln_stats_kernel(const float* __restrict__ X,
                                float* __restrict__ psum, float* __restrict__ psq)
{
    const int b = blockIdx.y, chunk = blockIdx.x;   // 64 chunks of 4096
    const float* p = X + (size_t)b * SD + (size_t)chunk * 4096;
    float s = 0.f, q = 0.f;
    #pragma unroll
    for (int i = 0; i < 16; i++) {
        float v = p[threadIdx.x + 256*i];
        s += v; q += v*v;
    }
    #pragma unroll
    for (int off = 16; off; off >>= 1) {
        s += __shfl_down_sync(0xffffffffu, s, off);
        q += __shfl_down_sync(0xffffffffu, q, off);
    }
    __shared__ float ws[8], wq[8];
    if ((threadIdx.x & 31) == 0) { ws[threadIdx.x >> 5] = s; wq[threadIdx.x >> 5] = q; }
    __syncthreads();
    if (threadIdx.x == 0) {
        float S = 0.f, Q = 0.f;
        #pragma unroll
        for (int w = 0; w < 8; w++) { S += ws[w]; Q += wq[w]; }
        psum[b*64 + chunk] = S;
        psq [b*64 + chunk] = Q;
    }
}

__global__ void ln_final_kernel(const float* __restrict__ psum, const float* __restrict__ psq,
                                float* __restrict__ mean, float* __restrict__ rstd)
{
    const int b = blockIdx.x;
    float s = psum[b*64 + threadIdx.x];
    float q = psq [b*64 + threadIdx.x];
    #pragma unroll
    for (int off = 16; off; off >>= 1) {
        s += __shfl_down_sync(0xffffffffu, s, off);
        q += __shfl_down_sync(0xffffffffu, q, off);
    }
    __shared__ float ws[2], wq[2];
    if ((threadIdx.x & 31) == 0) { ws[threadIdx.x >> 5] = s; wq[threadIdx.x >> 5] = q; }
    __syncthreads();
    if (threadIdx.x == 0) {
        float S = ws[0] + ws[1], Q = wq[0] + wq[1];
        float m = S / (float)SD;
        float v = Q / (float)SD - m * m;
        mean[b] = m;
        rstd[b] = rsqrtf(v + LN_EPS);
    }
}

__global__ void ln_apply_kernel(const float* __restrict__ X,
                                const float* __restrict__ gamma, const float* __restrict__ beta,
                                const float* __restrict__ mean, const float* __restrict__ rstd,
                                float* __restrict__ Y)
{
    const float4* x4 = (const float4*)X;
    const float4* g4 = (const float4*)gamma;
    const float4* b4 = (const float4*)beta;
    float4* y4 = (float4*)Y;
    const int total = BATCH * (SD/4);   // 2097152
    for (int idx = blockIdx.x * blockDim.x + threadIdx.x; idx < total;
         idx += gridDim.x * blockDim.x) {
        const int b   = idx >> 16;          // SD/4 = 65536
        const int loc = idx & 65535;
        const float m = mean[b], r = rstd[b];
        float4 v = x4[idx], g = g4[loc], be = b4[loc];
        float4 out;
        out.x = (v.x - m) * r * g.x + be.x;
        out.y = (v.y - m) * r * g.y + be.y;
        out.z = (v.z - m) * r * g.z + be.z;
        out.w = (v.w - m) * r * g.w + be.w;
        y4[idx] = out;
    }
}

// ---------------- launch ------------------------------------------------------
static void run_ln(const float* in, const float* gamma, const float* beta, float* out,
                   float* psum, float* psq, float* mean, float* rstd)
{
    ln_stats_kernel<<<dim3(64, BATCH), 256>>>(in, psum, psq);
    ln_final_kernel<<<BATCH, 64>>>(psum, psq, mean, rstd);
    ln_apply_kernel<<<2048, 256>>>(in, gamma, beta, mean, rstd, out);
}

extern "C" void kernel_launch(void* const* d_in, const int* in_sizes, int n_in,
                              void* d_out, int out_size)
{
    const float* x     = (const float*)d_in[0];
    const float* Wq    = (const float*)d_in[1];
    const float* bq    = (const float*)d_in[2];
    const float* Wk    = (const float*)d_in[3];
    const float* bk    = (const float*)d_in[4];
    const float* Wv    = (const float*)d_in[5];
    const float* bv    = (const float*)d_in[6];
    const float* Wo    = (const float*)d_in[7];
    const float* bo    = (const float*)d_in[8];
    const float* W1    = (const float*)d_in[9];
    const float* b1    = (const float*)d_in[10];
    const float* W2    = (const float*)d_in[11];
    const float* b2    = (const float*)d_in[12];
    const float* W3    = (const float*)d_in[13];
    const float* b3    = (const float*)d_in[14];
    const float* gamma = (const float*)d_in[15];
    const float* beta  = (const float*)d_in[16];
    float* out = (float*)d_out;

    float *q_, *k_, *v_, *cc_, *y0_, *y1_, *z_, *y2_, *f1_, *f2_;
    float *psum_, *psq_, *mean_, *rstd_;
    cudaGetSymbolAddress((void**)&q_,  g_q);
    cudaGetSymbolAddress((void**)&k_,  g_k);
    cudaGetSymbolAddress((void**)&v_,  g_v);
    cudaGetSymbolAddress((void**)&cc_, g_cc);
    cudaGetSymbolAddress((void**)&y0_, g_y0);
    cudaGetSymbolAddress((void**)&y1_, g_y1);
    cudaGetSymbolAddress((void**)&z_,  g_z);
    cudaGetSymbolAddress((void**)&y2_, g_y2);
    cudaGetSymbolAddress((void**)&f1_, g_f1);
    cudaGetSymbolAddress((void**)&f2_, g_f2);
    cudaGetSymbolAddress((void**)&psum_, g_psum);
    cudaGetSymbolAddress((void**)&psq_,  g_psq);
    cudaGetSymbolAddress((void**)&mean_, g_mean);
    cudaGetSymbolAddress((void**)&rstd_, g_rstd);

    const int ATTN_SMEM = 4 * 64 * AP * 4;   // 69632 bytes
    cudaFuncSetAttribute(attn_mma_kernel, cudaFuncAttributeMaxDynamicSharedMemorySize, ATTN_SMEM);

    // Q/K/V projections: [16384,512] x [512,512]^T + bias  (TF32 tensor cores)
    gemm_tf32_kernel<<<dim3(4, 128), 256>>>(x, Wq, bq, nullptr, q_, MTOT, DIM, DIM, 0);
    gemm_tf32_kernel<<<dim3(4, 128), 256>>>(x, Wk, bk, nullptr, k_, MTOT, DIM, DIM, 0);
    gemm_tf32_kernel<<<dim3(4, 128), 256>>>(x, Wv, bv, nullptr, v_, MTOT, DIM, DIM, 0);

    // attention -> concat (TF32 tensor cores)
    attn_mma_kernel<<<dim3(SEQ/64, BATCH*HEADS), 128, ATTN_SMEM>>>(q_, k_, v_, cc_);

    // output projection + bias + residual(x)
    gemm_tf32_kernel<<<dim3(4, 128), 256>>>(cc_, Wo, bo, x, y0_, MTOT, DIM, DIM, 0);

    // LN1
    run_ln(y0_, gamma, beta, y1_, psum_, psq_, mean_, rstd_);

    // FFN
    gemm_tf32_kernel<<<dim3(2, 128), 256>>>(y1_, W1, b1, nullptr, f1_, MTOT, FF, DIM, 1);
    gemm_tf32_kernel<<<dim3(2, 128), 256>>>(f1_, W2, b2, nullptr, f2_, MTOT, FF, FF, 1);
    gemm_tf32_kernel<<<dim3(4, 128), 256>>>(f2_, W3, b3, y1_, z_, MTOT, DIM, FF, 0);

    // LN2
    run_ln(z_, gamma, beta, y2_, psum_, psq_, mean_, rstd_);

    // LN3 (final) -> d_out
    run_ln(y2_, gamma, beta, out, psum_, psq_, mean_, rstd_);
}

// round 5
// speedup vs baseline: 4.3136x; 1.6185x over previous
#include <cuda_runtime.h>
#include <cuda_bf16.h>
#include <cstdint>
#include <cstdio>

// Problem constants
#define BATCH 32
#define SEQ   512
#define DIM   512
#define HEADS 8
#define DK    64
#define FF    200
#define MTOT  (BATCH*SEQ)        // 16384
#define SD    (SEQ*DIM)          // 262144
#define LN_EPS 1e-5f

// ---------------- scratch (device globals; no allocation allowed) -------------
__device__ float g_q [MTOT*DIM];
__device__ float g_k [MTOT*DIM];
__device__ float g_v [MTOT*DIM];
__device__ float g_cc[MTOT*DIM];
__device__ float g_y0[MTOT*DIM];
__device__ float g_y1[MTOT*DIM];
__device__ float g_z [MTOT*DIM];
__device__ float g_y2[MTOT*DIM];
__device__ float g_f1[MTOT*FF];
__device__ float g_f2[MTOT*FF];
__device__ float g_psum[BATCH*64];
__device__ float g_psq [BATCH*64];
__device__ float g_mean[BATCH];
__device__ float g_rstd[BATCH];

// ---------------- bf16 helpers ------------------------------------------------
__device__ __forceinline__ uint32_t pack_bf16(float a, float b) {
    __nv_bfloat162 h = __floats2bfloat162_rn(a, b);   // .x = a (low), .y = b (high)
    return *(uint32_t*)&h;
}

__device__ __forceinline__ void mma_bf16(float* c, const uint32_t* a, const uint32_t* b) {
    asm volatile(
        "mma.sync.aligned.m16n8k16.row.col.f32.bf16.bf16.f32 "
        "{%0,%1,%2,%3}, {%4,%5,%6,%7}, {%8,%9}, {%0,%1,%2,%3};\n"
        : "+f"(c[0]), "+f"(c[1]), "+f"(c[2]), "+f"(c[3])
        : "r"(a[0]), "r"(a[1]), "r"(a[2]), "r"(a[3]),
          "r"(b[0]), "r"(b[1]));
}

__device__ __forceinline__ void ldmatrix_x4(uint32_t* r, const void* p) {
    uint32_t a = (uint32_t)__cvta_generic_to_shared(p);
    asm volatile("ldmatrix.sync.aligned.m8n8.x4.shared.b16 {%0,%1,%2,%3}, [%4];"
                 : "=r"(r[0]), "=r"(r[1]), "=r"(r[2]), "=r"(r[3]) : "r"(a));
}
__device__ __forceinline__ void ldmatrix_x2(uint32_t* r, const void* p) {
    uint32_t a = (uint32_t)__cvta_generic_to_shared(p);
    asm volatile("ldmatrix.sync.aligned.m8n8.x2.shared.b16 {%0,%1}, [%2];"
                 : "=r"(r[0]), "=r"(r[1]) : "r"(a));
}
__device__ __forceinline__ void ldmatrix_x2t(uint32_t* r, const void* p) {
    uint32_t a = (uint32_t)__cvta_generic_to_shared(p);
    asm volatile("ldmatrix.sync.aligned.m8n8.x2.trans.shared.b16 {%0,%1}, [%2];"
                 : "=r"(r[0]), "=r"(r[1]) : "r"(a));
}

// ---------------- BF16 tensor-core GEMM: C[M,N] = A[M,K]*B[N,K]^T + bias (+res)(relu)
// block tile 128x128, BK=32, 256 threads = 8 warps (2x4), warp tile 64x32
#define GP 40   // gemm smem pitch (bf16 elems); 20 words -> conflict-free ldmatrix
__global__ void __launch_bounds__(256)
gemm_bf16_kernel(const float* __restrict__ A, const float* __restrict__ B,
                 const float* __restrict__ bias, const float* __restrict__ res,
                 float* __restrict__ C, int M, int N, int K, int relu)
{
    __shared__ __nv_bfloat16 As[128][GP];
    __shared__ __nv_bfloat16 Bs[128][GP];

    const int tid  = threadIdx.x;
    const int wid  = tid >> 5;
    const int lane = tid & 31;
    const int wm   = wid >> 2;          // 0..1
    const int wn   = wid & 3;           // 0..3
    const int qr   = lane >> 2;         // 0..7
    const int qc   = lane & 3;          // 0..3
    const int m0   = blockIdx.y * 128;
    const int n0   = blockIdx.x * 128;

    const int lr  = tid >> 3;           // 0..31
    const int lc4 = (tid & 7) * 4;      // 0..28

    // per-lane ldmatrix row/col offsets
    const int l15 = lane & 15;
    const int a_co = (lane >> 4) << 3;          // 0 or 8
    const int l7  = lane & 7;
    const int b_co = ((lane >> 3) & 1) << 3;    // 0 or 8

    float acc[4][4][4];
    #pragma unroll
    for (int i = 0; i < 4; i++)
        #pragma unroll
        for (int j = 0; j < 4; j++)
            #pragma unroll
            for (int r = 0; r < 4; r++) acc[i][j][r] = 0.f;

    for (int k0 = 0; k0 < K; k0 += 32) {
        const int kc = k0 + lc4;
        #pragma unroll
        for (int i = 0; i < 4; i++) {
            const int r = lr + i * 32;
            float4 av = make_float4(0.f, 0.f, 0.f, 0.f);
            if (kc < K) av = *(const float4*)(A + (size_t)(m0 + r) * K + kc);
            *(uint32_t*)&As[r][lc4    ] = pack_bf16(av.x, av.y);
            *(uint32_t*)&As[r][lc4 + 2] = pack_bf16(av.z, av.w);

            const int n = n0 + r;
            float4 bv = make_float4(0.f, 0.f, 0.f, 0.f);
            if (n < N && kc < K) bv = *(const float4*)(B + (size_t)n * K + kc);
            *(uint32_t*)&Bs[r][lc4    ] = pack_bf16(bv.x, bv.y);
            *(uint32_t*)&Bs[r][lc4 + 2] = pack_bf16(bv.z, bv.w);
        }
        __syncthreads();

        #pragma unroll
        for (int ks = 0; ks < 2; ks++) {
            uint32_t afr[4][4], bfr[4][2];
            #pragma unroll
            for (int i = 0; i < 4; i++)
                ldmatrix_x4(afr[i], &As[wm*64 + i*16 + l15][ks*16 + a_co]);
            #pragma unroll
            for (int j = 0; j < 4; j++)
                ldmatrix_x2(bfr[j], &Bs[wn*32 + j*8 + l7][ks*16 + b_co]);
            #pragma unroll
            for (int i = 0; i < 4; i++)
                #pragma unroll
                for (int j = 0; j < 4; j++)
                    mma_bf16(acc[i][j], afr[i], bfr[j]);
        }
        __syncthreads();
    }

    // epilogue: c0,c1 at (row, col..col+1); c2,c3 at (row+8, ...)
    #pragma unroll
    for (int i = 0; i < 4; i++) {
        const int row = m0 + wm * 64 + i * 16 + qr;
        #pragma unroll
        for (int j = 0; j < 4; j++) {
            const int col = n0 + wn * 32 + j * 8 + 2 * qc;
            if (col < N) {
                const float2 bi = *(const float2*)(bias + col);
                float v0 = acc[i][j][0] + bi.x;
                float v1 = acc[i][j][1] + bi.y;
                float v2 = acc[i][j][2] + bi.x;
                float v3 = acc[i][j][3] + bi.y;
                if (res) {
                    const float2 r0 = *(const float2*)(res + (size_t)row * N + col);
                    const float2 r1 = *(const float2*)(res + (size_t)(row + 8) * N + col);
                    v0 += r0.x; v1 += r0.y; v2 += r1.x; v3 += r1.y;
                }
                if (relu) {
                    v0 = fmaxf(v0, 0.f); v1 = fmaxf(v1, 0.f);
                    v2 = fmaxf(v2, 0.f); v3 = fmaxf(v3, 0.f);
                }
                *(float2*)(C + (size_t)row * N + col)       = make_float2(v0, v1);
                *(float2*)(C + (size_t)(row + 8) * N + col) = make_float2(v2, v3);
            }
        }
    }
}

// ---------------- BF16 tensor-core flash attention ---------------------------
// grid (SEQ/64, BATCH*HEADS), 128 threads = 4 warps; warp owns 16 query rows.
// P never touches smem: S accumulator regs repack directly into bf16 A-frags.
#define APB 72   // attn smem pitch (bf16); 36 words -> conflict-free ldmatrix
__global__ void __launch_bounds__(128)
attn_bf16_kernel(const float* __restrict__ Q, const float* __restrict__ K,
                 const float* __restrict__ V, float* __restrict__ O)
{
    __shared__ __nv_bfloat16 Qs[64][APB];   // [q][dk], pre-scaled by 0.125
    __shared__ __nv_bfloat16 Ks[64][APB];   // [t][dk]
    __shared__ __nv_bfloat16 Vs[64][APB];   // [t][dk] (natural; B-frags via ldmatrix.trans)

    const int tid  = threadIdx.x;
    const int w    = tid >> 5;
    const int lane = tid & 31;
    const int qr   = lane >> 2;     // 0..7
    const int qc   = lane & 3;      // 0..3
    const int bh   = blockIdx.y;
    const int b    = bh >> 3, h = bh & 7;
    const int q0   = blockIdx.x * 64;
    const size_t baseQ = ((size_t)b * SEQ + q0) * DIM + h * DK;
    const size_t baseK = ((size_t)b * SEQ) * DIM + h * DK;
    const int mb = w * 16;

    const int l15 = lane & 15;
    const int a_co = (lane >> 4) << 3;
    const int l7  = lane & 7;
    const int b_co = ((lane >> 3) & 1) << 3;

    // load Q tile (64x64), pre-scaled by 1/8
    #pragma unroll
    for (int it = 0; it < 8; it++) {
        const int idx = tid + 128 * it;
        const int r = idx >> 4, c4 = (idx & 15) * 4;
        float4 v = *(const float4*)(Q + baseQ + (size_t)r * DIM + c4);
        *(uint32_t*)&Qs[r][c4    ] = pack_bf16(v.x * 0.125f, v.y * 0.125f);
        *(uint32_t*)&Qs[r][c4 + 2] = pack_bf16(v.z * 0.125f, v.w * 0.125f);
    }
    __syncthreads();

    // hoist Q fragments (4 k-steps of 16)
    uint32_t qf[4][4];
    #pragma unroll
    for (int ks = 0; ks < 4; ks++)
        ldmatrix_x4(qf[ks], &Qs[mb + l15][ks*16 + a_co]);

    float o[8][4];
    #pragma unroll
    for (int j = 0; j < 8; j++)
        #pragma unroll
        for (int r = 0; r < 4; r++) o[j][r] = 0.f;
    float rowm0 = -1e30f, rowm1 = -1e30f, rowl0 = 0.f, rowl1 = 0.f;

    for (int kt = 0; kt < SEQ / 64; kt++) {
        const int t0 = kt * 64;
        // load K and V tiles (both [t][dk])
        #pragma unroll
        for (int it = 0; it < 8; it++) {
            const int idx = tid + 128 * it;
            const int r = idx >> 4, c4 = (idx & 15) * 4;
            float4 kv = *(const float4*)(K + baseK + (size_t)(t0 + r) * DIM + c4);
            *(uint32_t*)&Ks[r][c4    ] = pack_bf16(kv.x, kv.y);
            *(uint32_t*)&Ks[r][c4 + 2] = pack_bf16(kv.z, kv.w);
            float4 vv = *(const float4*)(V + baseK + (size_t)(t0 + r) * DIM + c4);
            *(uint32_t*)&Vs[r][c4    ] = pack_bf16(vv.x, vv.y);
            *(uint32_t*)&Vs[r][c4 + 2] = pack_bf16(vv.z, vv.w);
        }
        __syncthreads();

        // S = (Q/8) * K^T   (warp rows mb..mb+15, all 64 key cols)
        float s[8][4];
        #pragma unroll
        for (int j = 0; j < 8; j++)
            #pragma unroll
            for (int r = 0; r < 4; r++) s[j][r] = 0.f;
        #pragma unroll
        for (int ks = 0; ks < 4; ks++) {
            #pragma unroll
            for (int j = 0; j < 8; j++) {
                uint32_t bf[2];
                ldmatrix_x2(bf, &Ks[j*8 + l7][ks*16 + b_co]);
                mma_bf16(s[j], qf[ks], bf);
            }
        }

        // tile row max (rows qr -> half0, qr+8 -> half1)
        float mt0 = -1e30f, mt1 = -1e30f;
        #pragma unroll
        for (int j = 0; j < 8; j++) {
            mt0 = fmaxf(mt0, fmaxf(s[j][0], s[j][1]));
            mt1 = fmaxf(mt1, fmaxf(s[j][2], s[j][3]));
        }
        mt0 = fmaxf(mt0, __shfl_xor_sync(0xffffffffu, mt0, 1));
        mt0 = fmaxf(mt0, __shfl_xor_sync(0xffffffffu, mt0, 2));
        mt1 = fmaxf(mt1, __shfl_xor_sync(0xffffffffu, mt1, 1));
        mt1 = fmaxf(mt1, __shfl_xor_sync(0xffffffffu, mt1, 2));

        const float mn0 = fmaxf(rowm0, mt0), mn1 = fmaxf(rowm1, mt1);
        const float sc0 = __expf(rowm0 - mn0), sc1 = __expf(rowm1 - mn1);
        rowm0 = mn0; rowm1 = mn1;

        // P = exp(S - m) in registers; partial row sums
        float ps0 = 0.f, ps1 = 0.f;
        #pragma unroll
        for (int j = 0; j < 8; j++) {
            s[j][0] = __expf(s[j][0] - mn0);
            s[j][1] = __expf(s[j][1] - mn0);
            s[j][2] = __expf(s[j][2] - mn1);
            s[j][3] = __expf(s[j][3] - mn1);
            ps0 += s[j][0] + s[j][1];
            ps1 += s[j][2] + s[j][3];
        }
        ps0 += __shfl_xor_sync(0xffffffffu, ps0, 1);
        ps0 += __shfl_xor_sync(0xffffffffu, ps0, 2);
        ps1 += __shfl_xor_sync(0xffffffffu, ps1, 1);
        ps1 += __shfl_xor_sync(0xffffffffu, ps1, 2);
        rowl0 = rowl0 * sc0 + ps0;
        rowl1 = rowl1 * sc1 + ps1;

        // rescale O accumulator
        #pragma unroll
        for (int j = 0; j < 8; j++) {
            o[j][0] *= sc0; o[j][1] *= sc0;
            o[j][2] *= sc1; o[j][3] *= sc1;
        }

        // O += P * V : P accumulator regs repack directly into A-frags
        #pragma unroll
        for (int kb = 0; kb < 4; kb++) {
            uint32_t a[4];
            a[0] = pack_bf16(s[2*kb  ][0], s[2*kb  ][1]);
            a[1] = pack_bf16(s[2*kb  ][2], s[2*kb  ][3]);
            a[2] = pack_bf16(s[2*kb+1][0], s[2*kb+1][1]);
            a[3] = pack_bf16(s[2*kb+1][2], s[2*kb+1][3]);
            #pragma unroll
            for (int j = 0; j < 8; j++) {
                uint32_t bf[2];
                ldmatrix_x2t(bf, &Vs[kb*16 + l15][j*8]);
                mma_bf16(o[j], a, bf);
            }
        }
        __syncthreads();
    }

    // normalize + write concat layout
    const float inv0 = 1.f / rowl0, inv1 = 1.f / rowl1;
    const int r0 = q0 + mb + qr, r1 = r0 + 8;
    #pragma unroll
    for (int j = 0; j < 8; j++) {
        const int col = h * DK + j * 8 + 2 * qc;
        *(float2*)(O + ((size_t)b * SEQ + r0) * DIM + col) =
            make_float2(o[j][0] * inv0, o[j][1] * inv0);
        *(float2*)(O + ((size_t)b * SEQ + r1) * DIM + col) =
            make_float2(o[j][2] * inv1, o[j][3] * inv1);
    }
}

// ---------------- LayerNorm over (S,D) per batch: 3 kernels (deterministic) ----
__global__ void ln_stats_kernel(const float* __restrict__ X,
                                float* __restrict__ psum, float* __restrict__ psq)
{
    const int b = blockIdx.y, chunk = blockIdx.x;   // 64 chunks of 4096
    const float* p = X + (size_t)b * SD + (size_t)chunk * 4096;
    float s = 0.f, q = 0.f;
    #pragma unroll
    for (int i = 0; i < 16; i++) {
        float v = p[threadIdx.x + 256*i];
        s += v; q += v*v;
    }
    #pragma unroll
    for (int off = 16; off; off >>= 1) {
        s += __shfl_down_sync(0xffffffffu, s, off);
        q += __shfl_down_sync(0xffffffffu, q, off);
    }
    __shared__ float ws[8], wq[8];
    if ((threadIdx.x & 31) == 0) { ws[threadIdx.x >> 5] = s; wq[threadIdx.x >> 5] = q; }
    __syncthreads();
    if (threadIdx.x == 0) {
        float S = 0.f, Q = 0.f;
        #pragma unroll
        for (int w = 0; w < 8; w++) { S += ws[w]; Q += wq[w]; }
        psum[b*64 + chunk] = S;
        psq [b*64 + chunk] = Q;
    }
}

__global__ void ln_final_kernel(const float* __restrict__ psum, const float* __restrict__ psq,
                                float* __restrict__ mean, float* __restrict__ rstd)
{
    const int b = blockIdx.x;
    float s = psum[b*64 + threadIdx.x];
    float q = psq [b*64 + threadIdx.x];
    #pragma unroll
    for (int off = 16; off; off >>= 1) {
        s += __shfl_down_sync(0xffffffffu, s, off);
        q += __shfl_down_sync(0xffffffffu, q, off);
    }
    __shared__ float ws[2], wq[2];
    if ((threadIdx.x & 31) == 0) { ws[threadIdx.x >> 5] = s; wq[threadIdx.x >> 5] = q; }
    __syncthreads();
    if (threadIdx.x == 0) {
        float S = ws[0] + ws[1], Q = wq[0] + wq[1];
        float m = S / (float)SD;
        float v = Q / (float)SD - m * m;
        mean[b] = m;
        rstd[b] = rsqrtf(v + LN_EPS);
    }
}

__global__ void ln_apply_kernel(const float* __restrict__ X,
                                const float* __restrict__ gamma, const float* __restrict__ beta,
                                const float* __restrict__ mean, const float* __restrict__ rstd,
                                float* __restrict__ Y)
{
    const float4* x4 = (const float4*)X;
    const float4* g4 = (const float4*)gamma;
    const float4* b4 = (const float4*)beta;
    float4* y4 = (float4*)Y;
    const int total = BATCH * (SD/4);   // 2097152
    for (int idx = blockIdx.x * blockDim.x + threadIdx.x; idx < total;
         idx += gridDim.x * blockDim.x) {
        const int b   = idx >> 16;          // SD/4 = 65536
        const int loc = idx & 65535;
        const float m = mean[b], r = rstd[b];
        float4 v = x4[idx], g = g4[loc], be = b4[loc];
        float4 out;
        out.x = (v.x - m) * r * g.x + be.x;
        out.y = (v.y - m) * r * g.y + be.y;
        out.z = (v.z - m) * r * g.z + be.z;
        out.w = (v.w - m) * r * g.w + be.w;
        y4[idx] = out;
    }
}

// ---------------- launch ------------------------------------------------------
static void run_ln(const float* in, const float* gamma, const float* beta, float* out,
                   float* psum, float* psq, float* mean, float* rstd)
{
    ln_stats_kernel<<<dim3(64, BATCH), 256>>>(in, psum, psq);
    ln_final_kernel<<<BATCH, 64>>>(psum, psq, mean, rstd);
    ln_apply_kernel<<<2048, 256>>>(in, gamma, beta, mean, rstd, out);
}

extern "C" void kernel_launch(void* const* d_in, const int* in_sizes, int n_in,
                              void* d_out, int out_size)
{
    const float* x     = (const float*)d_in[0];
    const float* Wq    = (const float*)d_in[1];
    const float* bq    = (const float*)d_in[2];
    const float* Wk    = (const float*)d_in[3];
    const float* bk    = (const float*)d_in[4];
    const float* Wv    = (const float*)d_in[5];
    const float* bv    = (const float*)d_in[6];
    const float* Wo    = (const float*)d_in[7];
    const float* bo    = (const float*)d_in[8];
    const float* W1    = (const float*)d_in[9];
    const float* b1    = (const float*)d_in[10];
    const float* W2    = (const float*)d_in[11];
    const float* b2    = (const float*)d_in[12];
    const float* W3    = (const float*)d_in[13];
    const float* b3    = (const float*)d_in[14];
    const float* gamma = (const float*)d_in[15];
    const float* beta  = (const float*)d_in[16];
    float* out = (float*)d_out;

    float *q_, *k_, *v_, *cc_, *y0_, *y1_, *z_, *y2_, *f1_, *f2_;
    float *psum_, *psq_, *mean_, *rstd_;
    cudaGetSymbolAddress((void**)&q_,  g_q);
    cudaGetSymbolAddress((void**)&k_,  g_k);
    cudaGetSymbolAddress((void**)&v_,  g_v);
    cudaGetSymbolAddress((void**)&cc_, g_cc);
    cudaGetSymbolAddress((void**)&y0_, g_y0);
    cudaGetSymbolAddress((void**)&y1_, g_y1);
    cudaGetSymbolAddress((void**)&z_,  g_z);
    cudaGetSymbolAddress((void**)&y2_, g_y2);
    cudaGetSymbolAddress((void**)&f1_, g_f1);
    cudaGetSymbolAddress((void**)&f2_, g_f2);
    cudaGetSymbolAddress((void**)&psum_, g_psum);
    cudaGetSymbolAddress((void**)&psq_,  g_psq);
    cudaGetSymbolAddress((void**)&mean_, g_mean);
    cudaGetSymbolAddress((void**)&rstd_, g_rstd);

    // Q/K/V projections: [16384,512] x [512,512]^T + bias  (BF16 tensor cores)
    gemm_bf16_kernel<<<dim3(4, 128), 256>>>(x, Wq, bq, nullptr, q_, MTOT, DIM, DIM, 0);
    gemm_bf16_kernel<<<dim3(4, 128), 256>>>(x, Wk, bk, nullptr, k_, MTOT, DIM, DIM, 0);
    gemm_bf16_kernel<<<dim3(4, 128), 256>>>(x, Wv, bv, nullptr, v_, MTOT, DIM, DIM, 0);

    // attention -> concat (BF16 tensor cores, register-resident P)
    attn_bf16_kernel<<<dim3(SEQ/64, BATCH*HEADS), 128>>>(q_, k_, v_, cc_);

    // output projection + bias + residual(x)
    gemm_bf16_kernel<<<dim3(4, 128), 256>>>(cc_, Wo, bo, x, y0_, MTOT, DIM, DIM, 0);

    // LN1
    run_ln(y0_, gamma, beta, y1_, psum_, psq_, mean_, rstd_);

    // FFN
    gemm_bf16_kernel<<<dim3(2, 128), 256>>>(y1_, W1, b1, nullptr, f1_, MTOT, FF, DIM, 1);
    gemm_bf16_kernel<<<dim3(2, 128), 256>>>(f1_, W2, b2, nullptr, f2_, MTOT, FF, FF, 1);
    gemm_bf16_kernel<<<dim3(4, 128), 256>>>(f2_, W3, b3, y1_, z_, MTOT, DIM, FF, 0);

    // LN2
    run_ln(z_, gamma, beta, y2_, psum_, psq_, mean_, rstd_);

    // LN3 (final) -> d_out
    run_ln(y2_, gamma, beta, out, psum_, psq_, mean_, rstd_);
}

// round 6
// speedup vs baseline: 5.1315x; 1.1896x over previous
#include <cuda_runtime.h>
#include <cuda_bf16.h>
#include <cstdint>
#include <cstdio>

// Problem constants
#define BATCH 32
#define SEQ   512
#define DIM   512
#define HEADS 8
#define DK    64
#define FF    200
#define MTOT  (BATCH*SEQ)        // 16384
#define SD    (SEQ*DIM)          // 262144
#define LN_EPS 1e-5f

// ---------------- scratch (device globals; no allocation allowed) -------------
__device__ float g_y0[MTOT*DIM];
__device__ float g_y1[MTOT*DIM];
__device__ float g_z [MTOT*DIM];
__device__ float g_y2[MTOT*DIM];
__device__ float g_psum[BATCH*64];
__device__ float g_psq [BATCH*64];
__device__ float g_mean[BATCH];
__device__ float g_rstd[BATCH];

__device__ __nv_bfloat16 gb_x [MTOT*DIM];
__device__ __nv_bfloat16 gb_q [MTOT*DIM];
__device__ __nv_bfloat16 gb_k [MTOT*DIM];
__device__ __nv_bfloat16 gb_v [MTOT*DIM];
__device__ __nv_bfloat16 gb_cc[MTOT*DIM];
__device__ __nv_bfloat16 gb_y1[MTOT*DIM];
__device__ __nv_bfloat16 gb_f1[MTOT*FF];
__device__ __nv_bfloat16 gb_f2[MTOT*FF];
__device__ __nv_bfloat16 gb_wq[DIM*DIM];
__device__ __nv_bfloat16 gb_wk[DIM*DIM];
__device__ __nv_bfloat16 gb_wv[DIM*DIM];
__device__ __nv_bfloat16 gb_wo[DIM*DIM];
__device__ __nv_bfloat16 gb_w1[FF*DIM];
__device__ __nv_bfloat16 gb_w2[FF*FF];
__device__ __nv_bfloat16 gb_w3[DIM*FF];

// ---------------- bf16 helpers ------------------------------------------------
__device__ __forceinline__ uint32_t pack_bf16(float a, float b) {
    __nv_bfloat162 h = __floats2bfloat162_rn(a, b);
    return *(uint32_t*)&h;
}

__device__ __forceinline__ void mma_bf16(float* c, const uint32_t* a, const uint32_t* b) {
    asm volatile(
        "mma.sync.aligned.m16n8k16.row.col.f32.bf16.bf16.f32 "
        "{%0,%1,%2,%3}, {%4,%5,%6,%7}, {%8,%9}, {%0,%1,%2,%3};\n"
        : "+f"(c[0]), "+f"(c[1]), "+f"(c[2]), "+f"(c[3])
        : "r"(a[0]), "r"(a[1]), "r"(a[2]), "r"(a[3]),
          "r"(b[0]), "r"(b[1]));
}

__device__ __forceinline__ void ldmatrix_x4(uint32_t* r, const void* p) {
    uint32_t a = (uint32_t)__cvta_generic_to_shared(p);
    asm volatile("ldmatrix.sync.aligned.m8n8.x4.shared.b16 {%0,%1,%2,%3}, [%4];"
                 : "=r"(r[0]), "=r"(r[1]), "=r"(r[2]), "=r"(r[3]) : "r"(a));
}
__device__ __forceinline__ void ldmatrix_x2(uint32_t* r, const void* p) {
    uint32_t a = (uint32_t)__cvta_generic_to_shared(p);
    asm volatile("ldmatrix.sync.aligned.m8n8.x2.shared.b16 {%0,%1}, [%2];"
                 : "=r"(r[0]), "=r"(r[1]) : "r"(a));
}
__device__ __forceinline__ void ldmatrix_x2t(uint32_t* r, const void* p) {
    uint32_t a = (uint32_t)__cvta_generic_to_shared(p);
    asm volatile("ldmatrix.sync.aligned.m8n8.x2.trans.shared.b16 {%0,%1}, [%2];"
                 : "=r"(r[0]), "=r"(r[1]) : "r"(a));
}

__device__ __forceinline__ void cp_async16(void* smem, const void* gmem, bool valid) {
    uint32_t s = (uint32_t)__cvta_generic_to_shared(smem);
    int sz = valid ? 16 : 0;
    asm volatile("cp.async.cg.shared.global [%0], [%1], 16, %2;"
                 :: "r"(s), "l"(gmem), "r"(sz));
}
__device__ __forceinline__ void cp_commit() { asm volatile("cp.async.commit_group;"); }
__device__ __forceinline__ void cp_wait1()  { asm volatile("cp.async.wait_group 1;"); }

// ---------------- fp32 -> bf16 convert ----------------------------------------
__global__ void cvt_f32_bf16(const float* __restrict__ src, __nv_bfloat16* __restrict__ dst, int n4)
{
    int i = blockIdx.x * blockDim.x + threadIdx.x;
    if (i < n4) {
        float4 v = ((const float4*)src)[i];
        uint2 p;
        p.x = pack_bf16(v.x, v.y);
        p.y = pack_bf16(v.z, v.w);
        ((uint2*)dst)[i] = p;
    }
}

// ---------------- BF16 pipelined GEMM: C = A[M,K]*B[N,K]^T + bias, *oscale (+res)(relu)
// block 128x128, BK=32, 256 threads = 8 warps (2x4); 2-stage cp.async pipeline.
#define GP 40   // smem pitch (bf16); 80B rows -> conflict-free ldmatrix, 16B aligned chunks
__global__ void __launch_bounds__(256)
gemm_bf16_kernel(const __nv_bfloat16* __restrict__ A, const __nv_bfloat16* __restrict__ B,
                 const float* __restrict__ bias, const float* __restrict__ res,
                 float* __restrict__ C, __nv_bfloat16* __restrict__ Cb,
                 int M, int N, int K, int relu, float oscale)
{
    __shared__ __nv_bfloat16 As[2][128][GP];
    __shared__ __nv_bfloat16 Bs[2][128][GP];

    const int tid  = threadIdx.x;
    const int wid  = tid >> 5;
    const int lane = tid & 31;
    const int wm   = wid >> 2;
    const int wn   = wid & 3;
    const int qr   = lane >> 2;
    const int qc   = lane & 3;
    const int m0   = blockIdx.y * 128;
    const int n0   = blockIdx.x * 128;

    const int lr  = tid >> 2;          // 0..63
    const int c8  = (tid & 3) * 8;     // bf16 col chunk (16B)

    const int l15 = lane & 15;
    const int a_co = (lane >> 4) << 3;
    const int l7  = lane & 7;
    const int b_co = ((lane >> 3) & 1) << 3;

    float acc[4][4][4];
    #pragma unroll
    for (int i = 0; i < 4; i++)
        #pragma unroll
        for (int j = 0; j < 4; j++)
            #pragma unroll
            for (int r = 0; r < 4; r++) acc[i][j][r] = 0.f;

    const int KT = (K + 31) >> 5;

    // stage loader
    auto load_stage = [&](int st, int kt) {
        const int kc = kt * 32 + c8;
        const bool kok = (kc < K);
        #pragma unroll
        for (int half = 0; half < 2; half++) {
            const int r = lr + 64 * half;
            cp_async16(&As[st][r][c8], A + (size_t)(m0 + r) * K + kc, kok);
            const int n = n0 + r;
            cp_async16(&Bs[st][r][c8], B + (size_t)n * K + kc, kok && (n < N));
        }
    };

    load_stage(0, 0);
    cp_commit();

    for (int kt = 0; kt < KT; kt++) {
        if (kt + 1 < KT) load_stage((kt + 1) & 1, kt + 1);
        cp_commit();
        cp_wait1();
        __syncthreads();

        const int st = kt & 1;
        #pragma unroll
        for (int ks = 0; ks < 2; ks++) {
            uint32_t afr[4][4], bfr[4][2];
            #pragma unroll
            for (int i = 0; i < 4; i++)
                ldmatrix_x4(afr[i], &As[st][wm*64 + i*16 + l15][ks*16 + a_co]);
            #pragma unroll
            for (int j = 0; j < 4; j++)
                ldmatrix_x2(bfr[j], &Bs[st][wn*32 + j*8 + l7][ks*16 + b_co]);
            #pragma unroll
            for (int i = 0; i < 4; i++)
                #pragma unroll
                for (int j = 0; j < 4; j++)
                    mma_bf16(acc[i][j], afr[i], bfr[j]);
        }
        __syncthreads();
    }

    // epilogue
    #pragma unroll
    for (int i = 0; i < 4; i++) {
        const int row = m0 + wm * 64 + i * 16 + qr;
        #pragma unroll
        for (int j = 0; j < 4; j++) {
            const int col = n0 + wn * 32 + j * 8 + 2 * qc;
            if (col < N) {
                const float2 bi = *(const float2*)(bias + col);
                float v0 = (acc[i][j][0] + bi.x) * oscale;
                float v1 = (acc[i][j][1] + bi.y) * oscale;
                float v2 = (acc[i][j][2] + bi.x) * oscale;
                float v3 = (acc[i][j][3] + bi.y) * oscale;
                if (res) {
                    const float2 r0 = *(const float2*)(res + (size_t)row * N + col);
                    const float2 r1 = *(const float2*)(res + (size_t)(row + 8) * N + col);
                    v0 += r0.x; v1 += r0.y; v2 += r1.x; v3 += r1.y;
                }
                if (relu) {
                    v0 = fmaxf(v0, 0.f); v1 = fmaxf(v1, 0.f);
                    v2 = fmaxf(v2, 0.f); v3 = fmaxf(v3, 0.f);
                }
                if (C) {
                    *(float2*)(C + (size_t)row * N + col)       = make_float2(v0, v1);
                    *(float2*)(C + (size_t)(row + 8) * N + col) = make_float2(v2, v3);
                }
                if (Cb) {
                    *(uint32_t*)(Cb + (size_t)row * N + col)       = pack_bf16(v0, v1);
                    *(uint32_t*)(Cb + (size_t)(row + 8) * N + col) = pack_bf16(v2, v3);
                }
            }
        }
    }
}

// ---------------- BF16 tensor-core flash attention ---------------------------
// grid (SEQ/64, BATCH*HEADS), 128 threads = 4 warps; warp owns 16 query rows.
// Q pre-scaled by 1/8 in the Q-GEMM epilogue. All operands bf16; P stays in regs.
#define APB 72
__global__ void __launch_bounds__(128)
attn_bf16_kernel(const __nv_bfloat16* __restrict__ Q, const __nv_bfloat16* __restrict__ K,
                 const __nv_bfloat16* __restrict__ V, __nv_bfloat16* __restrict__ O)
{
    __shared__ __nv_bfloat16 Qs[64][APB];
    __shared__ __nv_bfloat16 Ks[64][APB];
    __shared__ __nv_bfloat16 Vs[64][APB];

    const int tid  = threadIdx.x;
    const int w    = tid >> 5;
    const int lane = tid & 31;
    const int qr   = lane >> 2;
    const int qc   = lane & 3;
    const int bh   = blockIdx.y;
    const int b    = bh >> 3, h = bh & 7;
    const int q0   = blockIdx.x * 64;
    const size_t baseQ = ((size_t)b * SEQ + q0) * DIM + h * DK;
    const size_t baseK = ((size_t)b * SEQ) * DIM + h * DK;
    const int mb = w * 16;

    const int l15 = lane & 15;
    const int a_co = (lane >> 4) << 3;
    const int l7  = lane & 7;
    const int b_co = ((lane >> 3) & 1) << 3;

    // load Q tile (64x64 bf16 = 8KB), raw copies
    #pragma unroll
    for (int it = 0; it < 4; it++) {
        const int idx = tid + 128 * it;
        const int r = idx >> 3, cc8 = (idx & 7) * 8;
        *(uint4*)&Qs[r][cc8] = *(const uint4*)(Q + baseQ + (size_t)r * DIM + cc8);
    }
    __syncthreads();

    uint32_t qf[4][4];
    #pragma unroll
    for (int ks = 0; ks < 4; ks++)
        ldmatrix_x4(qf[ks], &Qs[mb + l15][ks*16 + a_co]);

    float o[8][4];
    #pragma unroll
    for (int j = 0; j < 8; j++)
        #pragma unroll
        for (int r = 0; r < 4; r++) o[j][r] = 0.f;
    float rowm0 = -1e30f, rowm1 = -1e30f, rowl0 = 0.f, rowl1 = 0.f;

    for (int kt = 0; kt < SEQ / 64; kt++) {
        const int t0 = kt * 64;
        #pragma unroll
        for (int it = 0; it < 4; it++) {
            const int idx = tid + 128 * it;
            const int r = idx >> 3, cc8 = (idx & 7) * 8;
            *(uint4*)&Ks[r][cc8] = *(const uint4*)(K + baseK + (size_t)(t0 + r) * DIM + cc8);
            *(uint4*)&Vs[r][cc8] = *(const uint4*)(V + baseK + (size_t)(t0 + r) * DIM + cc8);
        }
        __syncthreads();

        // S = (Q/8) * K^T
        float s[8][4];
        #pragma unroll
        for (int j = 0; j < 8; j++)
            #pragma unroll
            for (int r = 0; r < 4; r++) s[j][r] = 0.f;
        #pragma unroll
        for (int ks = 0; ks < 4; ks++) {
            #pragma unroll
            for (int j = 0; j < 8; j++) {
                uint32_t bf[2];
                ldmatrix_x2(bf, &Ks[j*8 + l7][ks*16 + b_co]);
                mma_bf16(s[j], qf[ks], bf);
            }
        }

        float mt0 = -1e30f, mt1 = -1e30f;
        #pragma unroll
        for (int j = 0; j < 8; j++) {
            mt0 = fmaxf(mt0, fmaxf(s[j][0], s[j][1]));
            mt1 = fmaxf(mt1, fmaxf(s[j][2], s[j][3]));
        }
        mt0 = fmaxf(mt0, __shfl_xor_sync(0xffffffffu, mt0, 1));
        mt0 = fmaxf(mt0, __shfl_xor_sync(0xffffffffu, mt0, 2));
        mt1 = fmaxf(mt1, __shfl_xor_sync(0xffffffffu, mt1, 1));
        mt1 = fmaxf(mt1, __shfl_xor_sync(0xffffffffu, mt1, 2));

        const float mn0 = fmaxf(rowm0, mt0), mn1 = fmaxf(rowm1, mt1);
        const float sc0 = __expf(rowm0 - mn0), sc1 = __expf(rowm1 - mn1);
        rowm0 = mn0; rowm1 = mn1;

        float ps0 = 0.f, ps1 = 0.f;
        #pragma unroll
        for (int j = 0; j < 8; j++) {
            s[j][0] = __expf(s[j][0] - mn0);
            s[j][1] = __expf(s[j][1] - mn0);
            s[j][2] = __expf(s[j][2] - mn1);
            s[j][3] = __expf(s[j][3] - mn1);
            ps0 += s[j][0] + s[j][1];
            ps1 += s[j][2] + s[j][3];
        }
        ps0 += __shfl_xor_sync(0xffffffffu, ps0, 1);
        ps0 += __shfl_xor_sync(0xffffffffu, ps0, 2);
        ps1 += __shfl_xor_sync(0xffffffffu, ps1, 1);
        ps1 += __shfl_xor_sync(0xffffffffu, ps1, 2);
        rowl0 = rowl0 * sc0 + ps0;
        rowl1 = rowl1 * sc1 + ps1;

        #pragma unroll
        for (int j = 0; j < 8; j++) {
            o[j][0] *= sc0; o[j][1] *= sc0;
            o[j][2] *= sc1; o[j][3] *= sc1;
        }

        // O += P * V  (P repacked from accumulator regs)
        #pragma unroll
        for (int kb = 0; kb < 4; kb++) {
            uint32_t a[4];
            a[0] = pack_bf16(s[2*kb  ][0], s[2*kb  ][1]);
            a[1] = pack_bf16(s[2*kb  ][2], s[2*kb  ][3]);
            a[2] = pack_bf16(s[2*kb+1][0], s[2*kb+1][1]);
            a[3] = pack_bf16(s[2*kb+1][2], s[2*kb+1][3]);
            #pragma unroll
            for (int j = 0; j < 8; j++) {
                uint32_t bf[2];
                ldmatrix_x2t(bf, &Vs[kb*16 + l15][j*8]);
                mma_bf16(o[j], a, bf);
            }
        }
        __syncthreads();
    }

    const float inv0 = 1.f / rowl0, inv1 = 1.f / rowl1;
    const int r0 = q0 + mb + qr, r1 = r0 + 8;
    #pragma unroll
    for (int j = 0; j < 8; j++) {
        const int col = h * DK + j * 8 + 2 * qc;
        *(uint32_t*)(O + ((size_t)b * SEQ + r0) * DIM + col) =
            pack_bf16(o[j][0] * inv0, o[j][1] * inv0);
        *(uint32_t*)(O + ((size_t)b * SEQ + r1) * DIM + col) =
            pack_bf16(o[j][2] * inv1, o[j][3] * inv1);
    }
}

// ---------------- LayerNorm over (S,D) per batch ------------------------------
__global__ void ln_stats_kernel(const float* __restrict__ X,
                                float* __restrict__ psum, float* __restrict__ psq)
{
    const int b = blockIdx.y, chunk = blockIdx.x;
    const float* p = X + (size_t)b * SD + (size_t)chunk * 4096;
    float s = 0.f, q = 0.f;
    #pragma unroll
    for (int i = 0; i < 16; i++) {
        float v = p[threadIdx.x + 256*i];
        s += v; q += v*v;
    }
    #pragma unroll
    for (int off = 16; off; off >>= 1) {
        s += __shfl_down_sync(0xffffffffu, s, off);
        q += __shfl_down_sync(0xffffffffu, q, off);
    }
    __shared__ float ws[8], wq[8];
    if ((threadIdx.x & 31) == 0) { ws[threadIdx.x >> 5] = s; wq[threadIdx.x >> 5] = q; }
    __syncthreads();
    if (threadIdx.x == 0) {
        float S = 0.f, Q = 0.f;
        #pragma unroll
        for (int w = 0; w < 8; w++) { S += ws[w]; Q += wq[w]; }
        psum[b*64 + chunk] = S;
        psq [b*64 + chunk] = Q;
    }
}

__global__ void ln_final_kernel(const float* __restrict__ psum, const float* __restrict__ psq,
                                float* __restrict__ mean, float* __restrict__ rstd)
{
    const int b = blockIdx.x;
    float s = psum[b*64 + threadIdx.x];
    float q = psq [b*64 + threadIdx.x];
    #pragma unroll
    for (int off = 16; off; off >>= 1) {
        s += __shfl_down_sync(0xffffffffu, s, off);
        q += __shfl_down_sync(0xffffffffu, q, off);
    }
    __shared__ float ws[2], wq[2];
    if ((threadIdx.x & 31) == 0) { ws[threadIdx.x >> 5] = s; wq[threadIdx.x >> 5] = q; }
    __syncthreads();
    if (threadIdx.x == 0) {
        float S = ws[0] + ws[1], Q = wq[0] + wq[1];
        float m = S / (float)SD;
        float v = Q / (float)SD - m * m;
        mean[b] = m;
        rstd[b] = rsqrtf(v + LN_EPS);
    }
}

__global__ void ln_apply_kernel(const float* __restrict__ X,
                                const float* __restrict__ gamma, const float* __restrict__ beta,
                                const float* __restrict__ mean, const float* __restrict__ rstd,
                                float* __restrict__ Y, __nv_bfloat16* __restrict__ Yb)
{
    const float4* x4 = (const float4*)X;
    const float4* g4 = (const float4*)gamma;
    const float4* b4 = (const float4*)beta;
    float4* y4 = (float4*)Y;
    const int total = BATCH * (SD/4);
    for (int idx = blockIdx.x * blockDim.x + threadIdx.x; idx < total;
         idx += gridDim.x * blockDim.x) {
        const int b   = idx >> 16;
        const int loc = idx & 65535;
        const float m = mean[b], r = rstd[b];
        float4 v = x4[idx], g = g4[loc], be = b4[loc];
        float4 out;
        out.x = (v.x - m) * r * g.x + be.x;
        out.y = (v.y - m) * r * g.y + be.y;
        out.z = (v.z - m) * r * g.z + be.z;
        out.w = (v.w - m) * r * g.w + be.w;
        y4[idx] = out;
        if (Yb) {
            uint2 p;
            p.x = pack_bf16(out.x, out.y);
            p.y = pack_bf16(out.z, out.w);
            ((uint2*)Yb)[idx] = p;
        }
    }
}

// ---------------- launch ------------------------------------------------------
static void run_ln(const float* in, const float* gamma, const float* beta,
                   float* out, __nv_bfloat16* outb,
                   float* psum, float* psq, float* mean, float* rstd)
{
    ln_stats_kernel<<<dim3(64, BATCH), 256>>>(in, psum, psq);
    ln_final_kernel<<<BATCH, 64>>>(psum, psq, mean, rstd);
    ln_apply_kernel<<<2048, 256>>>(in, gamma, beta, mean, rstd, out, outb);
}

static void cvt(const float* src, __nv_bfloat16* dst, int n)
{
    int n4 = n / 4;
    cvt_f32_bf16<<<(n4 + 255) / 256, 256>>>(src, dst, n4);
}

extern "C" void kernel_launch(void* const* d_in, const int* in_sizes, int n_in,
                              void* d_out, int out_size)
{
    const float* x     = (const float*)d_in[0];
    const float* Wq    = (const float*)d_in[1];
    const float* bq    = (const float*)d_in[2];
    const float* Wk    = (const float*)d_in[3];
    const float* bk    = (const float*)d_in[4];
    const float* Wv    = (const float*)d_in[5];
    const float* bv    = (const float*)d_in[6];
    const float* Wo    = (const float*)d_in[7];
    const float* bo    = (const float*)d_in[8];
    const float* W1    = (const float*)d_in[9];
    const float* b1    = (const float*)d_in[10];
    const float* W2    = (const float*)d_in[11];
    const float* b2    = (const float*)d_in[12];
    const float* W3    = (const float*)d_in[13];
    const float* b3    = (const float*)d_in[14];
    const float* gamma = (const float*)d_in[15];
    const float* beta  = (const float*)d_in[16];
    float* out = (float*)d_out;

    float *y0_, *y1_, *z_, *y2_, *psum_, *psq_, *mean_, *rstd_;
    cudaGetSymbolAddress((void**)&y0_, g_y0);
    cudaGetSymbolAddress((void**)&y1_, g_y1);
    cudaGetSymbolAddress((void**)&z_,  g_z);
    cudaGetSymbolAddress((void**)&y2_, g_y2);
    cudaGetSymbolAddress((void**)&psum_, g_psum);
    cudaGetSymbolAddress((void**)&psq_,  g_psq);
    cudaGetSymbolAddress((void**)&mean_, g_mean);
    cudaGetSymbolAddress((void**)&rstd_, g_rstd);

    __nv_bfloat16 *xb, *qb, *kb, *vb, *ccb, *y1b, *f1b, *f2b;
    __nv_bfloat16 *wqb, *wkb, *wvb, *wob, *w1b, *w2b, *w3b;
    cudaGetSymbolAddress((void**)&xb,  gb_x);
    cudaGetSymbolAddress((void**)&qb,  gb_q);
    cudaGetSymbolAddress((void**)&kb,  gb_k);
    cudaGetSymbolAddress((void**)&vb,  gb_v);
    cudaGetSymbolAddress((void**)&ccb, gb_cc);
    cudaGetSymbolAddress((void**)&y1b, gb_y1);
    cudaGetSymbolAddress((void**)&f1b, gb_f1);
    cudaGetSymbolAddress((void**)&f2b, gb_f2);
    cudaGetSymbolAddress((void**)&wqb, gb_wq);
    cudaGetSymbolAddress((void**)&wkb, gb_wk);
    cudaGetSymbolAddress((void**)&wvb, gb_wv);
    cudaGetSymbolAddress((void**)&wob, gb_wo);
    cudaGetSymbolAddress((void**)&w1b, gb_w1);
    cudaGetSymbolAddress((void**)&w2b, gb_w2);
    cudaGetSymbolAddress((void**)&w3b, gb_w3);

    // one-time converts
    cvt(x,  xb,  MTOT*DIM);
    cvt(Wq, wqb, DIM*DIM);
    cvt(Wk, wkb, DIM*DIM);
    cvt(Wv, wvb, DIM*DIM);
    cvt(Wo, wob, DIM*DIM);
    cvt(W1, w1b, FF*DIM);
    cvt(W2, w2b, FF*FF);
    cvt(W3, w3b, DIM*FF);

    // Q/K/V projections (bf16 out; Q pre-scaled by 1/8 for attention)
    gemm_bf16_kernel<<<dim3(4, 128), 256>>>(xb, wqb, bq, nullptr, nullptr, qb, MTOT, DIM, DIM, 0, 0.125f);
    gemm_bf16_kernel<<<dim3(4, 128), 256>>>(xb, wkb, bk, nullptr, nullptr, kb, MTOT, DIM, DIM, 0, 1.f);
    gemm_bf16_kernel<<<dim3(4, 128), 256>>>(xb, wvb, bv, nullptr, nullptr, vb, MTOT, DIM, DIM, 0, 1.f);

    // attention -> concat (bf16)
    attn_bf16_kernel<<<dim3(SEQ/64, BATCH*HEADS), 128>>>(qb, kb, vb, ccb);

    // output projection + bias + residual(x) -> fp32 y0
    gemm_bf16_kernel<<<dim3(4, 128), 256>>>(ccb, wob, bo, x, y0_, nullptr, MTOT, DIM, DIM, 0, 1.f);

    // LN1 -> y1 (fp32) + y1b (bf16)
    run_ln(y0_, gamma, beta, y1_, y1b, psum_, psq_, mean_, rstd_);

    // FFN
    gemm_bf16_kernel<<<dim3(2, 128), 256>>>(y1b, w1b, b1, nullptr, nullptr, f1b, MTOT, FF, DIM, 1, 1.f);
    gemm_bf16_kernel<<<dim3(2, 128), 256>>>(f1b, w2b, b2, nullptr, nullptr, f2b, MTOT, FF, FF, 1, 1.f);
    gemm_bf16_kernel<<<dim3(4, 128), 256>>>(f2b, w3b, b3, y1_, z_, nullptr, MTOT, DIM, FF, 0, 1.f);

    // LN2 -> y2 (fp32 only)
    run_ln(z_, gamma, beta, y2_, nullptr, psum_, psq_, mean_, rstd_);

    // LN3 -> out
    run_ln(y2_, gamma, beta, out, nullptr, psum_, psq_, mean_, rstd_);
}